// round 7
// baseline (speedup 1.0000x reference)
#include <cuda_runtime.h>
#include <cstdint>

#define N_NODES 25000
#define N_EDGES 400000
#define D       128
#define N_LAYERS 3
#define N_GRAPHS 512
#define D_OUT   10

typedef unsigned long long ull;

// ---------------- device scratch ----------------
__device__ float g_h[N_NODES * D];
__device__ float g_agg[N_NODES * D];
__device__ float g_z[N_NODES * D];
__device__ int   g_deg[N_NODES];
__device__ int   g_off[N_NODES + 1];
__device__ int   g_cur[N_NODES];
__device__ int   g_col[N_EDGES];

// ---------------- f32x2 packed helpers ----------
__device__ __forceinline__ void fma2(ull& d, ull a, ull b, ull c) {
    asm("fma.rn.f32x2 %0, %1, %2, %3;" : "=l"(d) : "l"(a), "l"(b), "l"(c));
}
__device__ __forceinline__ ull pack2(float x) {
    ull r; unsigned xi = __float_as_uint(x);
    asm("mov.b64 %0, {%1, %2};" : "=l"(r) : "r"(xi), "r"(xi));
    return r;
}
__device__ __forceinline__ float2 unpack2(ull v) {
    unsigned lo, hi;
    asm("mov.b64 {%0, %1}, %2;" : "=r"(lo), "=r"(hi) : "l"(v));
    return make_float2(__uint_as_float(lo), __uint_as_float(hi));
}

// ---------------- CSR build ----------------
__global__ void k_hist(const int* __restrict__ ei) {
    int e = blockIdx.x * blockDim.x + threadIdx.x;
    if (e < N_EDGES) atomicAdd(&g_deg[ei[N_EDGES + e]], 1);
}

__global__ void k_scan() {
    const int ITEMS = 25;
    __shared__ int wsum[32];
    int tid = threadIdx.x;
    int lane = tid & 31, warp = tid >> 5;
    int base = tid * ITEMS;
    int v[ITEMS];
    int s = 0;
    #pragma unroll
    for (int i = 0; i < ITEMS; i++) {
        int idx = base + i;
        v[i] = (idx < N_NODES) ? g_deg[idx] : 0;
        s += v[i];
    }
    int x = s;
    #pragma unroll
    for (int o = 1; o < 32; o <<= 1) {
        int y = __shfl_up_sync(0xFFFFFFFFu, x, o);
        if (lane >= o) x += y;
    }
    if (lane == 31) wsum[warp] = x;
    __syncthreads();
    if (tid < 32) {
        int w = wsum[tid];
        #pragma unroll
        for (int o = 1; o < 32; o <<= 1) {
            int y = __shfl_up_sync(0xFFFFFFFFu, w, o);
            if (tid >= o) w += y;
        }
        wsum[tid] = w;
    }
    __syncthreads();
    int excl = x - s + ((warp > 0) ? wsum[warp - 1] : 0);
    #pragma unroll
    for (int i = 0; i < ITEMS; i++) {
        int idx = base + i;
        if (idx < N_NODES) { g_off[idx] = excl; g_cur[idx] = excl; }
        excl += v[i];
    }
    if (tid == 1023) g_off[N_NODES] = excl;
}

__global__ void k_fill(const int* __restrict__ ei) {
    int e = blockIdx.x * blockDim.x + threadIdx.x;
    if (e < N_EDGES) {
        int s = ei[e];
        int d = ei[N_EDGES + e];
        int pos = atomicAdd(&g_cur[d], 1);
        g_col[pos] = s;
    }
}

// ---------------- GIN aggregation: one warp per node ----------------
__global__ void k_agg(const float* __restrict__ hin, const float* __restrict__ eps, int layer) {
    int gt = blockIdx.x * blockDim.x + threadIdx.x;
    int node = gt >> 5;
    if (node >= N_NODES) return;
    int lane = gt & 31;
    float epsv = 1.0f + eps[layer];
    const float4* h4 = (const float4*)hin;
    float4 self = h4[(size_t)node * 32 + lane];
    float4 acc;
    acc.x = self.x * epsv; acc.y = self.y * epsv;
    acc.z = self.z * epsv; acc.w = self.w * epsv;
    int e = g_off[node], end = g_off[node + 1];
    for (; e + 3 < end; e += 4) {
        int c0 = g_col[e], c1 = g_col[e + 1], c2 = g_col[e + 2], c3 = g_col[e + 3];
        float4 v0 = h4[(size_t)c0 * 32 + lane];
        float4 v1 = h4[(size_t)c1 * 32 + lane];
        float4 v2 = h4[(size_t)c2 * 32 + lane];
        float4 v3 = h4[(size_t)c3 * 32 + lane];
        acc.x += (v0.x + v1.x) + (v2.x + v3.x);
        acc.y += (v0.y + v1.y) + (v2.y + v3.y);
        acc.z += (v0.z + v1.z) + (v2.z + v3.z);
        acc.w += (v0.w + v1.w) + (v2.w + v3.w);
    }
    for (; e < end; e++) {
        int c = g_col[e];
        float4 v = h4[(size_t)c * 32 + lane];
        acc.x += v.x; acc.y += v.y; acc.z += v.z; acc.w += v.w;
    }
    ((float4*)g_agg)[(size_t)node * 32 + lane] = acc;
}

// ---------------- GEMM: [M,128]@[128,128], 64x64 tiles, dup-A smem ---------
// 256 threads = 8 warps. Warp w owns cols [n0+w*8, n0+w*8+8) -> B loads are
// warp-broadcast (2x LDS.128 per k). A is stored in smem TRANSPOSED and
// DUPLICATED: AsT[k][r] is a 64-bit word with A[r][k] in both halves, so the
// mainloop LDS.64 directly feeds FFMA2 (no per-k pack MOVs).
// Thread: rows (l, l+32) x 8 cols = 16 FFMA2/k with 4 LDS/k (ratio 1.25).
// smem 64KB (AsT) + 32KB (B) = 96KB -> 2 CTA/SM.
// MODE 0: relu(acc*s + t) (BN eval fused);  MODE 1: relu(acc + bias)
#define TILE_M 64
#define TILE_N 64
#define GEMM_SMEM (TILE_M * D * 8 + D * TILE_N * 4)   // 65536 + 32768 = 98304

template <int MODE>
__global__ void __launch_bounds__(256, 2) k_gemm(
    const float* __restrict__ A, const float* __restrict__ W, float* __restrict__ C,
    int M,
    const float* __restrict__ bias, const float* __restrict__ gamma,
    const float* __restrict__ beta, const float* __restrict__ mean,
    const float* __restrict__ var)
{
    extern __shared__ char smem_raw[];
    ull*   AsT = (ull*)smem_raw;                       // [128 k][64 r] dup'd
    float* Bs  = (float*)(smem_raw + TILE_M * D * 8);  // [128 k][64 c]
    int tid = threadIdx.x;
    int m0 = blockIdx.x * TILE_M;
    int n0 = blockIdx.y * TILE_N;

    // ---- prologue: A tile -> transposed + duplicated smem ----
    // idx: r = idx & 63 (lane-consecutive rows -> conflict-free STS),
    //      c4 = idx >> 6 (float4 chunk of k)
    {
        const float4* A4 = (const float4*)A;
        #pragma unroll
        for (int i = 0; i < 8; i++) {
            int idx = tid + i * 256;          // 0..2047
            int r  = idx & 63;
            int c4 = idx >> 6;                // 0..31
            int row = m0 + r;
            float4 v = (row < M) ? A4[(size_t)row * 32 + c4]
                                 : make_float4(0.f, 0.f, 0.f, 0.f);
            int k0 = c4 * 4;
            AsT[(k0 + 0) * TILE_M + r] = pack2(v.x);
            AsT[(k0 + 1) * TILE_M + r] = pack2(v.y);
            AsT[(k0 + 2) * TILE_M + r] = pack2(v.z);
            AsT[(k0 + 3) * TILE_M + r] = pack2(v.w);
        }
    }
    // ---- prologue: B tile (coalesced LDG, conflict-free STS) ----
    {
        #pragma unroll
        for (int i = 0; i < 8; i++) {
            int idx = tid + i * 256;          // 0..2047
            int k  = idx >> 4;                // 0..127
            int c4 = idx & 15;                // 0..15
            float4 v = *(const float4*)(W + (size_t)k * D + n0 + c4 * 4);
            *(float4*)(Bs + k * TILE_N + c4 * 4) = v;
        }
    }
    __syncthreads();

    int warp = tid >> 5;
    int lane = tid & 31;
    int c0 = warp * 8;                        // warp's col base within tile

    ull acc[2][4];
    #pragma unroll
    for (int j = 0; j < 2; j++)
        #pragma unroll
        for (int p = 0; p < 4; p++) acc[j][p] = 0ull;

    const ull* a0p = AsT + lane;
    const ull* a1p = AsT + lane + 32;
    const float* bp = Bs + c0;

    #pragma unroll 4
    for (int k = 0; k < D; k++) {
        ull a0 = a0p[k * TILE_M];
        ull a1 = a1p[k * TILE_M];
        ulonglong2 b01 = *(const ulonglong2*)(bp + k * TILE_N);      // cols c0..c0+3
        ulonglong2 b23 = *(const ulonglong2*)(bp + k * TILE_N + 4);  // cols c0+4..c0+7
        fma2(acc[0][0], a0, b01.x, acc[0][0]);
        fma2(acc[0][1], a0, b01.y, acc[0][1]);
        fma2(acc[0][2], a0, b23.x, acc[0][2]);
        fma2(acc[0][3], a0, b23.y, acc[0][3]);
        fma2(acc[1][0], a1, b01.x, acc[1][0]);
        fma2(acc[1][1], a1, b01.y, acc[1][1]);
        fma2(acc[1][2], a1, b23.x, acc[1][2]);
        fma2(acc[1][3], a1, b23.y, acc[1][3]);
    }

    // ---- epilogue: per-col constants (warp-broadcast LDGs), fused BN/ReLU ----
    float sc[8], sh[8];
    #pragma unroll
    for (int c = 0; c < 8; c++) {
        int col = n0 + c0 + c;
        if (MODE == 0) {
            float s = gamma[col] * rsqrtf(var[col] + 1e-5f);
            sc[c] = s;
            sh[c] = (bias[col] - mean[col]) * s + beta[col];
        } else {
            sc[c] = 1.0f;
            sh[c] = bias[col];
        }
    }

    #pragma unroll
    for (int j = 0; j < 2; j++) {
        int row = m0 + lane + 32 * j;
        if (row < M) {
            float o[8];
            #pragma unroll
            for (int p = 0; p < 4; p++) {
                float2 v = unpack2(acc[j][p]);
                o[2*p]     = fmaxf(fmaf(v.x, sc[2*p],     sh[2*p]),     0.f);
                o[2*p + 1] = fmaxf(fmaf(v.y, sc[2*p + 1], sh[2*p + 1]), 0.f);
            }
            float* cp = C + (size_t)row * D + n0 + c0;
            *(float4*)(cp)     = make_float4(o[0], o[1], o[2], o[3]);
            *(float4*)(cp + 4) = make_float4(o[4], o[5], o[6], o[7]);
        }
    }
}

// ---------------- mean-pool per graph + final linear ----------------
__global__ void k_pool(const float* __restrict__ h, const int* __restrict__ batch,
                       const float* __restrict__ Wout, const float* __restrict__ bout,
                       float* __restrict__ out)
{
    int g = blockIdx.x;
    int t = threadIdx.x;   // 128

    int lo = 0, hi = N_NODES;
    while (lo < hi) { int mid = (lo + hi) >> 1; if (batch[mid] < g) lo = mid + 1; else hi = mid; }
    int start = lo;
    lo = start; hi = N_NODES;
    while (lo < hi) { int mid = (lo + hi) >> 1; if (batch[mid] < g + 1) lo = mid + 1; else hi = mid; }
    int stop = lo;

    float s = 0.f;
    for (int n = start; n < stop; n++) s += h[(size_t)n * D + t];
    float cnt = fmaxf((float)(stop - start), 1.f);

    __shared__ float sp[D];
    sp[t] = s / cnt;
    __syncthreads();

    if (t < D_OUT) {
        float acc = bout[t];
        #pragma unroll 8
        for (int k = 0; k < D; k++) acc += sp[k] * Wout[k * D_OUT + t];
        out[g * D_OUT + t] = acc;
    }
}

// ---------------- host launcher ----------------
extern "C" void kernel_launch(void* const* d_in, const int* in_sizes, int n_in,
                              void* d_out, int out_size)
{
    const float* x     = (const float*)d_in[0];
    const int*   ei    = (const int*)d_in[1];    // int32 (JAX x64 disabled)
    const int*   batch = (const int*)d_in[2];
    const float* W1    = (const float*)d_in[3];
    const float* b1    = (const float*)d_in[4];
    const float* gamma = (const float*)d_in[5];
    const float* beta  = (const float*)d_in[6];
    const float* rmean = (const float*)d_in[7];
    const float* rvar  = (const float*)d_in[8];
    const float* W2    = (const float*)d_in[9];
    const float* b2    = (const float*)d_in[10];
    const float* eps   = (const float*)d_in[11];
    const float* Wout  = (const float*)d_in[12];
    const float* bout  = (const float*)d_in[13];
    float* out = (float*)d_out;

    float *p_h, *p_agg, *p_z;
    int* p_deg;
    cudaGetSymbolAddress((void**)&p_h,   g_h);
    cudaGetSymbolAddress((void**)&p_agg, g_agg);
    cudaGetSymbolAddress((void**)&p_z,   g_z);
    cudaGetSymbolAddress((void**)&p_deg, g_deg);

    cudaFuncSetAttribute(k_gemm<0>, cudaFuncAttributeMaxDynamicSharedMemorySize, GEMM_SMEM);
    cudaFuncSetAttribute(k_gemm<1>, cudaFuncAttributeMaxDynamicSharedMemorySize, GEMM_SMEM);

    // ---- CSR build (recomputed every call: deterministic) ----
    cudaMemsetAsync(p_deg, 0, N_NODES * sizeof(int));
    k_hist<<<(N_EDGES + 255) / 256, 256>>>(ei);
    k_scan<<<1, 1024>>>();
    k_fill<<<(N_EDGES + 255) / 256, 256>>>(ei);

    const dim3 gemm_grid((N_NODES + TILE_M - 1) / TILE_M, D / TILE_N);  // 391 x 2
    const int agg_blocks = (N_NODES * 32 + 255) / 256;

    for (int l = 0; l < N_LAYERS; l++) {
        const float* hin = (l == 0) ? x : p_h;
        k_agg<<<agg_blocks, 256>>>(hin, eps, l);
        k_gemm<0><<<gemm_grid, 256, GEMM_SMEM>>>(
            p_agg, W1 + (size_t)l * D * D, p_z, N_NODES,
            b1 + l * D, gamma + l * D, beta + l * D, rmean + l * D, rvar + l * D);
        k_gemm<1><<<gemm_grid, 256, GEMM_SMEM>>>(
            p_z, W2 + (size_t)l * D * D, p_h, N_NODES,
            b2 + l * D, (const float*)0, (const float*)0, (const float*)0, (const float*)0);
    }

    k_pool<<<N_GRAPHS, D>>>(p_h, batch, Wout, bout, out);
}

// round 8
// speedup vs baseline: 1.2456x; 1.2456x over previous
#include <cuda_runtime.h>
#include <cstdint>

#define N_NODES 25000
#define N_EDGES 400000
#define D       128
#define N_LAYERS 3
#define N_GRAPHS 512
#define D_OUT   10

typedef unsigned long long ull;

// ---------------- device scratch ----------------
__device__ float g_h[N_NODES * D];
__device__ float g_agg[N_NODES * D];
__device__ float g_z[N_NODES * D];
__device__ int   g_deg[N_NODES];
__device__ int   g_off[N_NODES + 1];
__device__ int   g_cur[N_NODES];
__device__ int   g_col[N_EDGES];

// ---------------- f32x2 packed helpers ----------
__device__ __forceinline__ void fma2(ull& d, ull a, ull b, ull c) {
    asm("fma.rn.f32x2 %0, %1, %2, %3;" : "=l"(d) : "l"(a), "l"(b), "l"(c));
}
__device__ __forceinline__ ull pack2(float x) {
    ull r; unsigned xi = __float_as_uint(x);
    asm("mov.b64 %0, {%1, %2};" : "=l"(r) : "r"(xi), "r"(xi));
    return r;
}
__device__ __forceinline__ float2 unpack2(ull v) {
    unsigned lo, hi;
    asm("mov.b64 {%0, %1}, %2;" : "=r"(lo), "=r"(hi) : "l"(v));
    return make_float2(__uint_as_float(lo), __uint_as_float(hi));
}

// ---------------- CSR build (4-edge ILP for atomic latency) ----------------
#define EDGE_Q (N_EDGES / 4)   // 100000

__global__ void k_hist(const int* __restrict__ ei) {
    int t = blockIdx.x * blockDim.x + threadIdx.x;
    if (t < EDGE_Q) {
        int d0 = ei[N_EDGES + t];
        int d1 = ei[N_EDGES + t + EDGE_Q];
        int d2 = ei[N_EDGES + t + 2 * EDGE_Q];
        int d3 = ei[N_EDGES + t + 3 * EDGE_Q];
        atomicAdd(&g_deg[d0], 1);
        atomicAdd(&g_deg[d1], 1);
        atomicAdd(&g_deg[d2], 1);
        atomicAdd(&g_deg[d3], 1);
    }
}

__global__ void k_scan() {
    const int ITEMS = 25;
    __shared__ int wsum[32];
    int tid = threadIdx.x;
    int lane = tid & 31, warp = tid >> 5;
    int base = tid * ITEMS;
    int v[ITEMS];
    int s = 0;
    #pragma unroll
    for (int i = 0; i < ITEMS; i++) {
        int idx = base + i;
        v[i] = (idx < N_NODES) ? g_deg[idx] : 0;
        s += v[i];
    }
    int x = s;
    #pragma unroll
    for (int o = 1; o < 32; o <<= 1) {
        int y = __shfl_up_sync(0xFFFFFFFFu, x, o);
        if (lane >= o) x += y;
    }
    if (lane == 31) wsum[warp] = x;
    __syncthreads();
    if (tid < 32) {
        int w = wsum[tid];
        #pragma unroll
        for (int o = 1; o < 32; o <<= 1) {
            int y = __shfl_up_sync(0xFFFFFFFFu, w, o);
            if (tid >= o) w += y;
        }
        wsum[tid] = w;
    }
    __syncthreads();
    int excl = x - s + ((warp > 0) ? wsum[warp - 1] : 0);
    #pragma unroll
    for (int i = 0; i < ITEMS; i++) {
        int idx = base + i;
        if (idx < N_NODES) { g_off[idx] = excl; g_cur[idx] = excl; }
        excl += v[i];
    }
    if (tid == 1023) g_off[N_NODES] = excl;
}

__global__ void k_fill(const int* __restrict__ ei) {
    int t = blockIdx.x * blockDim.x + threadIdx.x;
    if (t < EDGE_Q) {
        #pragma unroll
        for (int i = 0; i < 4; i++) {
            int e = t + i * EDGE_Q;
            int s = ei[e];
            int d = ei[N_EDGES + e];
            int pos = atomicAdd(&g_cur[d], 1);
            g_col[pos] = s;
        }
    }
}

// ---------------- GIN aggregation: one warp per node ----------------
__global__ void k_agg(const float* __restrict__ hin, const float* __restrict__ eps, int layer) {
    int gt = blockIdx.x * blockDim.x + threadIdx.x;
    int node = gt >> 5;
    if (node >= N_NODES) return;
    int lane = gt & 31;
    float epsv = 1.0f + eps[layer];
    const float4* h4 = (const float4*)hin;
    float4 self = h4[(size_t)node * 32 + lane];
    float4 acc;
    acc.x = self.x * epsv; acc.y = self.y * epsv;
    acc.z = self.z * epsv; acc.w = self.w * epsv;
    int e = g_off[node], end = g_off[node + 1];
    for (; e + 3 < end; e += 4) {
        int c0 = g_col[e], c1 = g_col[e + 1], c2 = g_col[e + 2], c3 = g_col[e + 3];
        float4 v0 = h4[(size_t)c0 * 32 + lane];
        float4 v1 = h4[(size_t)c1 * 32 + lane];
        float4 v2 = h4[(size_t)c2 * 32 + lane];
        float4 v3 = h4[(size_t)c3 * 32 + lane];
        acc.x += (v0.x + v1.x) + (v2.x + v3.x);
        acc.y += (v0.y + v1.y) + (v2.y + v3.y);
        acc.z += (v0.z + v1.z) + (v2.z + v3.z);
        acc.w += (v0.w + v1.w) + (v2.w + v3.w);
    }
    for (; e < end; e++) {
        int c = g_col[e];
        float4 v = h4[(size_t)c * 32 + lane];
        acc.x += v.x; acc.y += v.y; acc.z += v.z; acc.w += v.w;
    }
    ((float4*)g_agg)[(size_t)node * 32 + lane] = acc;
}

// ---------------- GEMM: [M,128]@[128,128], 96x128 tile (R5 winner) ---------
// 256 threads = 8 warps. Warp w owns columns [w*16, w*16+16).
// Lane l accumulates rows l, l+32, l+64 (3x16 microtile, 24 FFMA2/k).
// B loads: warp-broadcast, now as 4x LDS.128 (was 8x LDS.64).
// A loads: stride-129 padding -> bank (lane+k)%32 -> conflict-free.
// smem 115072B -> 2 CTA/SM; grid 261 CTAs ~ one wave.
// MODE 0: relu(acc*s + t) (BN eval fused);  MODE 1: relu(acc + bias)
#define TILE_M    96
#define AS_STRIDE 129
#define GEMM_SMEM ((TILE_M * AS_STRIDE + D * D) * 4)   // 49536 + 65536 = 115072

template <int MODE>
__global__ void __launch_bounds__(256, 2) k_gemm(
    const float* __restrict__ A, const float* __restrict__ W, float* __restrict__ C,
    int M,
    const float* __restrict__ bias, const float* __restrict__ gamma,
    const float* __restrict__ beta, const float* __restrict__ mean,
    const float* __restrict__ var)
{
    extern __shared__ float smem[];
    float* As = smem;                          // 96 x 129 (padded)
    float* Bs = smem + TILE_M * AS_STRIDE;     // 128 x 128
    int tid = threadIdx.x;
    int m0 = blockIdx.x * TILE_M;

    // load B (4096 float4, direct copy)
    {
        const float4* W4 = (const float4*)W;
        float4* Bs4 = (float4*)Bs;
        #pragma unroll
        for (int i = 0; i < 16; i++) Bs4[tid + i * 256] = W4[tid + i * 256];
    }
    // load A tile -> stride-129 smem (scalar stores; padded rows)
    {
        #pragma unroll
        for (int i = 0; i < 12; i++) {
            int idx = tid + i * 256;            // 0..3071 float4-chunks
            int r  = idx >> 5;
            int c0 = (idx & 31) * 4;
            int row = m0 + r;
            float4 v = (row < M) ? *(const float4*)(A + (size_t)row * D + c0)
                                 : make_float4(0.f, 0.f, 0.f, 0.f);
            float* dst = As + r * AS_STRIDE + c0;
            dst[0] = v.x; dst[1] = v.y; dst[2] = v.z; dst[3] = v.w;
        }
    }
    __syncthreads();

    int warp = tid >> 5;
    int lane = tid & 31;
    int n0 = warp * 16;

    ull acc[3][8];
    #pragma unroll
    for (int j = 0; j < 3; j++)
        #pragma unroll
        for (int p = 0; p < 8; p++) acc[j][p] = 0ull;

    const float* a0 = As + lane * AS_STRIDE;
    const float* a1 = As + (lane + 32) * AS_STRIDE;
    const float* a2p = As + (lane + 64) * AS_STRIDE;
    const float* bp = Bs + n0;

    #pragma unroll 4
    for (int k = 0; k < D; k++) {
        // 16 B floats, broadcast, via 2x 16B vector LDS
        ulonglong2 q0 = *(const ulonglong2*)(bp + (size_t)k * D);
        ulonglong2 q1 = *(const ulonglong2*)(bp + (size_t)k * D + 4);
        ulonglong2 q2 = *(const ulonglong2*)(bp + (size_t)k * D + 8);
        ulonglong2 q3 = *(const ulonglong2*)(bp + (size_t)k * D + 12);
        ull b0 = q0.x, b1 = q0.y, b2 = q1.x, b3 = q1.y;
        ull b4 = q2.x, b5 = q2.y, b6 = q3.x, b7 = q3.y;
        ull x0 = pack2(a0[k]);
        ull x1 = pack2(a1[k]);
        ull x2 = pack2(a2p[k]);
        fma2(acc[0][0], x0, b0, acc[0][0]); fma2(acc[0][1], x0, b1, acc[0][1]);
        fma2(acc[0][2], x0, b2, acc[0][2]); fma2(acc[0][3], x0, b3, acc[0][3]);
        fma2(acc[0][4], x0, b4, acc[0][4]); fma2(acc[0][5], x0, b5, acc[0][5]);
        fma2(acc[0][6], x0, b6, acc[0][6]); fma2(acc[0][7], x0, b7, acc[0][7]);
        fma2(acc[1][0], x1, b0, acc[1][0]); fma2(acc[1][1], x1, b1, acc[1][1]);
        fma2(acc[1][2], x1, b2, acc[1][2]); fma2(acc[1][3], x1, b3, acc[1][3]);
        fma2(acc[1][4], x1, b4, acc[1][4]); fma2(acc[1][5], x1, b5, acc[1][5]);
        fma2(acc[1][6], x1, b6, acc[1][6]); fma2(acc[1][7], x1, b7, acc[1][7]);
        fma2(acc[2][0], x2, b0, acc[2][0]); fma2(acc[2][1], x2, b1, acc[2][1]);
        fma2(acc[2][2], x2, b2, acc[2][2]); fma2(acc[2][3], x2, b3, acc[2][3]);
        fma2(acc[2][4], x2, b4, acc[2][4]); fma2(acc[2][5], x2, b5, acc[2][5]);
        fma2(acc[2][6], x2, b6, acc[2][6]); fma2(acc[2][7], x2, b7, acc[2][7]);
    }

    // epilogue constants into As (free scratch now): s[128] at As[0..], t at As[128..]
    __syncthreads();
    if (tid < 128) {
        float s, t;
        if (MODE == 0) {
            s = gamma[tid] * rsqrtf(var[tid] + 1e-5f);
            t = (bias[tid] - mean[tid]) * s + beta[tid];
        } else {
            s = 1.0f; t = bias[tid];
        }
        As[tid] = s;
        As[128 + tid] = t;
    }
    __syncthreads();

    float sc[16], sh[16];
    #pragma unroll
    for (int c = 0; c < 16; c++) { sc[c] = As[n0 + c]; sh[c] = As[128 + n0 + c]; }

    #pragma unroll
    for (int j = 0; j < 3; j++) {
        int row = m0 + lane + 32 * j;
        if (row < M) {
            float* cp = C + (size_t)row * D + n0;
            #pragma unroll
            for (int p = 0; p < 8; p++) {
                float2 v = unpack2(acc[j][p]);
                float o0 = fmaxf(fmaf(v.x, sc[2*p],     sh[2*p]),     0.f);
                float o1 = fmaxf(fmaf(v.y, sc[2*p + 1], sh[2*p + 1]), 0.f);
                *(float2*)(cp + 2 * p) = make_float2(o0, o1);
            }
        }
    }
}

// ---------------- mean-pool per graph + final linear ----------------
__global__ void k_pool(const float* __restrict__ h, const int* __restrict__ batch,
                       const float* __restrict__ Wout, const float* __restrict__ bout,
                       float* __restrict__ out)
{
    int g = blockIdx.x;
    int t = threadIdx.x;   // 128

    int lo = 0, hi = N_NODES;
    while (lo < hi) { int mid = (lo + hi) >> 1; if (batch[mid] < g) lo = mid + 1; else hi = mid; }
    int start = lo;
    lo = start; hi = N_NODES;
    while (lo < hi) { int mid = (lo + hi) >> 1; if (batch[mid] < g + 1) lo = mid + 1; else hi = mid; }
    int stop = lo;

    float s = 0.f;
    for (int n = start; n < stop; n++) s += h[(size_t)n * D + t];
    float cnt = fmaxf((float)(stop - start), 1.f);

    __shared__ float sp[D];
    sp[t] = s / cnt;
    __syncthreads();

    if (t < D_OUT) {
        float acc = bout[t];
        #pragma unroll 8
        for (int k = 0; k < D; k++) acc += sp[k] * Wout[k * D_OUT + t];
        out[g * D_OUT + t] = acc;
    }
}

// ---------------- host launcher ----------------
extern "C" void kernel_launch(void* const* d_in, const int* in_sizes, int n_in,
                              void* d_out, int out_size)
{
    const float* x     = (const float*)d_in[0];
    const int*   ei    = (const int*)d_in[1];    // int32 (JAX x64 disabled)
    const int*   batch = (const int*)d_in[2];
    const float* W1    = (const float*)d_in[3];
    const float* b1    = (const float*)d_in[4];
    const float* gamma = (const float*)d_in[5];
    const float* beta  = (const float*)d_in[6];
    const float* rmean = (const float*)d_in[7];
    const float* rvar  = (const float*)d_in[8];
    const float* W2    = (const float*)d_in[9];
    const float* b2    = (const float*)d_in[10];
    const float* eps   = (const float*)d_in[11];
    const float* Wout  = (const float*)d_in[12];
    const float* bout  = (const float*)d_in[13];
    float* out = (float*)d_out;

    float *p_h, *p_agg, *p_z;
    int* p_deg;
    cudaGetSymbolAddress((void**)&p_h,   g_h);
    cudaGetSymbolAddress((void**)&p_agg, g_agg);
    cudaGetSymbolAddress((void**)&p_z,   g_z);
    cudaGetSymbolAddress((void**)&p_deg, g_deg);

    cudaFuncSetAttribute(k_gemm<0>, cudaFuncAttributeMaxDynamicSharedMemorySize, GEMM_SMEM);
    cudaFuncSetAttribute(k_gemm<1>, cudaFuncAttributeMaxDynamicSharedMemorySize, GEMM_SMEM);

    // ---- CSR build (recomputed every call: deterministic) ----
    cudaMemsetAsync(p_deg, 0, N_NODES * sizeof(int));
    k_hist<<<(EDGE_Q + 255) / 256, 256>>>(ei);
    k_scan<<<1, 1024>>>();
    k_fill<<<(EDGE_Q + 255) / 256, 256>>>(ei);

    const int gemm_blocks = (N_NODES + TILE_M - 1) / TILE_M;   // 261
    const int agg_blocks  = (N_NODES * 32 + 255) / 256;

    for (int l = 0; l < N_LAYERS; l++) {
        const float* hin = (l == 0) ? x : p_h;
        k_agg<<<agg_blocks, 256>>>(hin, eps, l);
        k_gemm<0><<<gemm_blocks, 256, GEMM_SMEM>>>(
            p_agg, W1 + (size_t)l * D * D, p_z, N_NODES,
            b1 + l * D, gamma + l * D, beta + l * D, rmean + l * D, rvar + l * D);
        k_gemm<1><<<gemm_blocks, 256, GEMM_SMEM>>>(
            p_z, W2 + (size_t)l * D * D, p_h, N_NODES,
            b2 + l * D, (const float*)0, (const float*)0, (const float*)0, (const float*)0);
    }

    k_pool<<<N_GRAPHS, D>>>(p_h, batch, Wout, bout, out);
}

// round 9
// speedup vs baseline: 1.4319x; 1.1496x over previous
#include <cuda_runtime.h>
#include <cstdint>

#define N_NODES 25000
#define N_EDGES 400000
#define D       128
#define N_LAYERS 3
#define N_GRAPHS 512
#define D_OUT   10

typedef unsigned long long ull;

// ---------------- device scratch ----------------
__device__ float g_h[N_NODES * D];
__device__ float g_agg[N_NODES * D];
__device__ int   g_deg[N_NODES];
__device__ int   g_off[N_NODES + 1];
__device__ int   g_cur[N_NODES];
__device__ int   g_col[N_EDGES];

// ---------------- f32x2 packed helpers ----------
__device__ __forceinline__ void fma2(ull& d, ull a, ull b, ull c) {
    asm("fma.rn.f32x2 %0, %1, %2, %3;" : "=l"(d) : "l"(a), "l"(b), "l"(c));
}
__device__ __forceinline__ ull pack2(float x) {
    ull r; unsigned xi = __float_as_uint(x);
    asm("mov.b64 %0, {%1, %2};" : "=l"(r) : "r"(xi), "r"(xi));
    return r;
}
__device__ __forceinline__ float2 unpack2(ull v) {
    unsigned lo, hi;
    asm("mov.b64 {%0, %1}, %2;" : "=r"(lo), "=r"(hi) : "l"(v));
    return make_float2(__uint_as_float(lo), __uint_as_float(hi));
}

// ---------------- CSR build (4-edge ILP) ----------------
#define EDGE_Q (N_EDGES / 4)   // 100000

__global__ void k_hist(const int* __restrict__ ei) {
    int t = blockIdx.x * blockDim.x + threadIdx.x;
    if (t < EDGE_Q) {
        int d0 = ei[N_EDGES + t];
        int d1 = ei[N_EDGES + t + EDGE_Q];
        int d2 = ei[N_EDGES + t + 2 * EDGE_Q];
        int d3 = ei[N_EDGES + t + 3 * EDGE_Q];
        atomicAdd(&g_deg[d0], 1);
        atomicAdd(&g_deg[d1], 1);
        atomicAdd(&g_deg[d2], 1);
        atomicAdd(&g_deg[d3], 1);
    }
}

__global__ void k_scan() {
    const int ITEMS = 25;
    __shared__ int wsum[32];
    int tid = threadIdx.x;
    int lane = tid & 31, warp = tid >> 5;
    int base = tid * ITEMS;
    int v[ITEMS];
    int s = 0;
    #pragma unroll
    for (int i = 0; i < ITEMS; i++) {
        int idx = base + i;
        v[i] = (idx < N_NODES) ? g_deg[idx] : 0;
        s += v[i];
    }
    int x = s;
    #pragma unroll
    for (int o = 1; o < 32; o <<= 1) {
        int y = __shfl_up_sync(0xFFFFFFFFu, x, o);
        if (lane >= o) x += y;
    }
    if (lane == 31) wsum[warp] = x;
    __syncthreads();
    if (tid < 32) {
        int w = wsum[tid];
        #pragma unroll
        for (int o = 1; o < 32; o <<= 1) {
            int y = __shfl_up_sync(0xFFFFFFFFu, w, o);
            if (tid >= o) w += y;
        }
        wsum[tid] = w;
    }
    __syncthreads();
    int excl = x - s + ((warp > 0) ? wsum[warp - 1] : 0);
    #pragma unroll
    for (int i = 0; i < ITEMS; i++) {
        int idx = base + i;
        if (idx < N_NODES) { g_off[idx] = excl; g_cur[idx] = excl; }
        excl += v[i];
    }
    if (tid == 1023) g_off[N_NODES] = excl;
}

__global__ void k_fill(const int* __restrict__ ei) {
    int t = blockIdx.x * blockDim.x + threadIdx.x;
    if (t < EDGE_Q) {
        #pragma unroll
        for (int i = 0; i < 4; i++) {
            int e = t + i * EDGE_Q;
            int s = ei[e];
            int d = ei[N_EDGES + e];
            int pos = atomicAdd(&g_cur[d], 1);
            g_col[pos] = s;
        }
    }
}

// ---------------- GIN aggregation: one warp per node ----------------
__global__ void k_agg(const float* __restrict__ hin, const float* __restrict__ eps, int layer) {
    int gt = blockIdx.x * blockDim.x + threadIdx.x;
    int node = gt >> 5;
    if (node >= N_NODES) return;
    int lane = gt & 31;
    float epsv = 1.0f + eps[layer];
    const float4* h4 = (const float4*)hin;
    float4 self = h4[(size_t)node * 32 + lane];
    float4 acc;
    acc.x = self.x * epsv; acc.y = self.y * epsv;
    acc.z = self.z * epsv; acc.w = self.w * epsv;
    int e = g_off[node], end = g_off[node + 1];
    for (; e + 3 < end; e += 4) {
        int c0 = g_col[e], c1 = g_col[e + 1], c2 = g_col[e + 2], c3 = g_col[e + 3];
        float4 v0 = h4[(size_t)c0 * 32 + lane];
        float4 v1 = h4[(size_t)c1 * 32 + lane];
        float4 v2 = h4[(size_t)c2 * 32 + lane];
        float4 v3 = h4[(size_t)c3 * 32 + lane];
        acc.x += (v0.x + v1.x) + (v2.x + v3.x);
        acc.y += (v0.y + v1.y) + (v2.y + v3.y);
        acc.z += (v0.z + v1.z) + (v2.z + v3.z);
        acc.w += (v0.w + v1.w) + (v2.w + v3.w);
    }
    for (; e < end; e++) {
        int c = g_col[e];
        float4 v = h4[(size_t)c * 32 + lane];
        acc.x += v.x; acc.y += v.y; acc.z += v.z; acc.w += v.w;
    }
    ((float4*)g_agg)[(size_t)node * 32 + lane] = acc;
}

// ---------------- fused layer: relu( relu(BN(A@W1)) @ W2 + b2 ) ------------
// TILE 192 rows x 128 cols, 384 threads, occ 1, grid 131 = one wave.
// Warp w: cols [(w&3)*32, +32), rows (w>>2)*64 + {lane, lane+32}.
// Per thread per k: 2 A-LDS.32 (conflict-free, odd stride) + 2 pack MOV +
// 8 B-LDS.128 (warp-broadcast) + 32 FFMA2. fma-pipe bound.
// z tile round-trips through the A smem scratch (sync-guarded overwrite).
#define FM 192
#define FSTRIDE 129
#define OFF_B1 (FM * FSTRIDE)             // 24768 floats
#define OFF_B2 (OFF_B1 + D * D)           // 41152
#define OFF_CONS (OFF_B2 + D * D)         // 57536
#define FUSED_SMEM ((OFF_CONS + 384) * 4) // 231680 B

__global__ void __launch_bounds__(384, 1) k_fused(
    const float* __restrict__ A, const float* __restrict__ W1,
    const float* __restrict__ W2, float* __restrict__ C, int M,
    const float* __restrict__ b1, const float* __restrict__ gamma,
    const float* __restrict__ beta, const float* __restrict__ mean,
    const float* __restrict__ var, const float* __restrict__ b2)
{
    extern __shared__ float sm[];
    float* As   = sm;               // 192 x 129 (A, later z)
    float* B1s  = sm + OFF_B1;      // 128 x 128
    float* B2s  = sm + OFF_B2;      // 128 x 128
    float* cons = sm + OFF_CONS;    // s[128], t[128], bias2[128]
    int tid = threadIdx.x;
    int m0 = blockIdx.x * FM;

    // ---- prologue ----
    {
        const float4* W14 = (const float4*)W1;
        const float4* W24 = (const float4*)W2;
        float4* B1s4 = (float4*)B1s;
        float4* B2s4 = (float4*)B2s;
        #pragma unroll
        for (int i = 0; i < 11; i++) {
            int idx = tid + i * 384;
            if (idx < 4096) { B1s4[idx] = W14[idx]; B2s4[idx] = W24[idx]; }
        }
        #pragma unroll
        for (int i = 0; i < 16; i++) {
            int idx = tid + i * 384;        // 0..6143
            int r = idx >> 5, c4 = idx & 31;
            int row = m0 + r;
            float4 v = (row < M) ? *(const float4*)(A + (size_t)row * D + c4 * 4)
                                 : make_float4(0.f, 0.f, 0.f, 0.f);
            float* dst = As + r * FSTRIDE + c4 * 4;
            dst[0] = v.x; dst[1] = v.y; dst[2] = v.z; dst[3] = v.w;
        }
        if (tid < 128) {
            float s = gamma[tid] * rsqrtf(var[tid] + 1e-5f);
            cons[tid]       = s;
            cons[128 + tid] = (b1[tid] - mean[tid]) * s + beta[tid];
            cons[256 + tid] = b2[tid];
        }
    }
    __syncthreads();

    int warp = tid >> 5;
    int lane = tid & 31;
    int cg = (warp & 3) * 32;       // col base
    int rg = (warp >> 2) * 64;      // row base

    ull acc[2][16];
    #pragma unroll
    for (int j = 0; j < 2; j++)
        #pragma unroll
        for (int p = 0; p < 16; p++) acc[j][p] = 0ull;

    const float* a0 = As + (rg + lane) * FSTRIDE;
    const float* a1 = a0 + 32 * FSTRIDE;

    // ---- GEMM1 ----
    {
        const float* bp = B1s + cg;
        #pragma unroll 2
        for (int k = 0; k < D; k++) {
            ull b[16];
            const ulonglong2* br = (const ulonglong2*)(bp + (size_t)k * D);
            #pragma unroll
            for (int q = 0; q < 8; q++) { ulonglong2 t2 = br[q]; b[2*q] = t2.x; b[2*q+1] = t2.y; }
            ull x0 = pack2(a0[k]);
            ull x1 = pack2(a1[k]);
            #pragma unroll
            for (int p = 0; p < 16; p++) {
                fma2(acc[0][p], x0, b[p], acc[0][p]);
                fma2(acc[1][p], x1, b[p], acc[1][p]);
            }
        }
    }

    // ---- BN + ReLU -> z back into As ----
    __syncthreads();          // everyone done reading A
    #pragma unroll
    for (int j = 0; j < 2; j++) {
        float* zr = As + (rg + lane + 32 * j) * FSTRIDE + cg;
        #pragma unroll
        for (int p = 0; p < 16; p++) {
            float2 v = unpack2(acc[j][p]);
            int c = 2 * p;
            zr[c]     = fmaxf(fmaf(v.x, cons[cg + c],     cons[128 + cg + c]),     0.f);
            zr[c + 1] = fmaxf(fmaf(v.y, cons[cg + c + 1], cons[128 + cg + c + 1]), 0.f);
        }
    }
    __syncthreads();          // z complete

    // ---- GEMM2 ----
    #pragma unroll
    for (int j = 0; j < 2; j++)
        #pragma unroll
        for (int p = 0; p < 16; p++) acc[j][p] = 0ull;
    {
        const float* bp = B2s + cg;
        #pragma unroll 2
        for (int k = 0; k < D; k++) {
            ull b[16];
            const ulonglong2* br = (const ulonglong2*)(bp + (size_t)k * D);
            #pragma unroll
            for (int q = 0; q < 8; q++) { ulonglong2 t2 = br[q]; b[2*q] = t2.x; b[2*q+1] = t2.y; }
            ull x0 = pack2(a0[k]);
            ull x1 = pack2(a1[k]);
            #pragma unroll
            for (int p = 0; p < 16; p++) {
                fma2(acc[0][p], x0, b[p], acc[0][p]);
                fma2(acc[1][p], x1, b[p], acc[1][p]);
            }
        }
    }

    // ---- bias + ReLU -> global ----
    #pragma unroll
    for (int j = 0; j < 2; j++) {
        int row = m0 + rg + lane + 32 * j;
        if (row < M) {
            float* cp = C + (size_t)row * D + cg;
            #pragma unroll
            for (int q = 0; q < 8; q++) {
                float2 v0 = unpack2(acc[j][2*q]);
                float2 v1 = unpack2(acc[j][2*q + 1]);
                float4 o;
                o.x = fmaxf(v0.x + cons[256 + cg + 4*q],     0.f);
                o.y = fmaxf(v0.y + cons[256 + cg + 4*q + 1], 0.f);
                o.z = fmaxf(v1.x + cons[256 + cg + 4*q + 2], 0.f);
                o.w = fmaxf(v1.y + cons[256 + cg + 4*q + 3], 0.f);
                *(float4*)(cp + 4 * q) = o;
            }
        }
    }
}

// ---------------- mean-pool per graph + final linear ----------------
__global__ void k_pool(const float* __restrict__ h, const int* __restrict__ batch,
                       const float* __restrict__ Wout, const float* __restrict__ bout,
                       float* __restrict__ out)
{
    int g = blockIdx.x;
    int t = threadIdx.x;   // 128

    int lo = 0, hi = N_NODES;
    while (lo < hi) { int mid = (lo + hi) >> 1; if (batch[mid] < g) lo = mid + 1; else hi = mid; }
    int start = lo;
    lo = start; hi = N_NODES;
    while (lo < hi) { int mid = (lo + hi) >> 1; if (batch[mid] < g + 1) lo = mid + 1; else hi = mid; }
    int stop = lo;

    float s = 0.f;
    for (int n = start; n < stop; n++) s += h[(size_t)n * D + t];
    float cnt = fmaxf((float)(stop - start), 1.f);

    __shared__ float sp[D];
    sp[t] = s / cnt;
    __syncthreads();

    if (t < D_OUT) {
        float acc = bout[t];
        #pragma unroll 8
        for (int k = 0; k < D; k++) acc += sp[k] * Wout[k * D_OUT + t];
        out[g * D_OUT + t] = acc;
    }
}

// ---------------- host launcher ----------------
extern "C" void kernel_launch(void* const* d_in, const int* in_sizes, int n_in,
                              void* d_out, int out_size)
{
    const float* x     = (const float*)d_in[0];
    const int*   ei    = (const int*)d_in[1];    // int32 (JAX x64 disabled)
    const int*   batch = (const int*)d_in[2];
    const float* W1    = (const float*)d_in[3];
    const float* b1    = (const float*)d_in[4];
    const float* gamma = (const float*)d_in[5];
    const float* beta  = (const float*)d_in[6];
    const float* rmean = (const float*)d_in[7];
    const float* rvar  = (const float*)d_in[8];
    const float* W2    = (const float*)d_in[9];
    const float* b2    = (const float*)d_in[10];
    const float* eps   = (const float*)d_in[11];
    const float* Wout  = (const float*)d_in[12];
    const float* bout  = (const float*)d_in[13];
    float* out = (float*)d_out;

    float *p_h, *p_agg;
    int* p_deg;
    cudaGetSymbolAddress((void**)&p_h,   g_h);
    cudaGetSymbolAddress((void**)&p_agg, g_agg);
    cudaGetSymbolAddress((void**)&p_deg, g_deg);

    cudaFuncSetAttribute(k_fused, cudaFuncAttributeMaxDynamicSharedMemorySize, FUSED_SMEM);

    // ---- CSR build (recomputed every call: deterministic) ----
    cudaMemsetAsync(p_deg, 0, N_NODES * sizeof(int));
    k_hist<<<(EDGE_Q + 255) / 256, 256>>>(ei);
    k_scan<<<1, 1024>>>();
    k_fill<<<(EDGE_Q + 255) / 256, 256>>>(ei);

    const int fused_blocks = (N_NODES + FM - 1) / FM;          // 131
    const int agg_blocks   = (N_NODES * 32 + 255) / 256;

    for (int l = 0; l < N_LAYERS; l++) {
        const float* hin = (l == 0) ? x : p_h;
        k_agg<<<agg_blocks, 256>>>(hin, eps, l);
        k_fused<<<fused_blocks, 384, FUSED_SMEM>>>(
            p_agg, W1 + (size_t)l * D * D, W2 + (size_t)l * D * D, p_h, N_NODES,
            b1 + l * D, gamma + l * D, beta + l * D, rmean + l * D, rvar + l * D,
            b2 + l * D);
    }

    k_pool<<<N_GRAPHS, D>>>(p_h, batch, Wout, bout, out);
}

// round 10
// speedup vs baseline: 1.5675x; 1.0947x over previous
#include <cuda_runtime.h>
#include <cstdint>

#define N_NODES 25000
#define N_EDGES 400000
#define D       128
#define N_LAYERS 3
#define N_GRAPHS 512
#define D_OUT   10

typedef unsigned long long ull;

// ---------------- device scratch ----------------
__device__ float    g_h[N_NODES * D];          // fp32 h3 (pool input)
__device__ unsigned g_hb[N_NODES * D / 2];     // bf16x2 h (agg input)
__device__ float    g_agg[N_NODES * D];
__device__ int      g_deg[N_NODES];
__device__ int      g_off[N_NODES + 1];
__device__ int      g_cur[N_NODES];
__device__ int      g_col[N_EDGES];

// ---------------- helpers ----------
__device__ __forceinline__ void fma2(ull& d, ull a, ull b, ull c) {
    asm("fma.rn.f32x2 %0, %1, %2, %3;" : "=l"(d) : "l"(a), "l"(b), "l"(c));
}
__device__ __forceinline__ ull pack2(float x) {
    ull r; unsigned xi = __float_as_uint(x);
    asm("mov.b64 %0, {%1, %2};" : "=l"(r) : "r"(xi), "r"(xi));
    return r;
}
__device__ __forceinline__ float2 unpack2(ull v) {
    unsigned lo, hi;
    asm("mov.b64 {%0, %1}, %2;" : "=r"(lo), "=r"(hi) : "l"(v));
    return make_float2(__uint_as_float(lo), __uint_as_float(hi));
}
// pack (e0,e1) -> bf16x2 (e0 in low half)
__device__ __forceinline__ unsigned bfpack(float e0, float e1) {
    unsigned r;
    asm("cvt.rn.bf16x2.f32 %0, %1, %2;" : "=r"(r) : "f"(e1), "f"(e0));
    return r;
}
__device__ __forceinline__ float bflo(unsigned p) { return __uint_as_float(p << 16); }
__device__ __forceinline__ float bfhi(unsigned p) { return __uint_as_float(p & 0xFFFF0000u); }

__device__ __forceinline__ uint32_t smem_u32(const void* p) {
    uint32_t a;
    asm("{ .reg .u64 t; cvta.to.shared.u64 t, %1; cvt.u32.u64 %0, t; }" : "=r"(a) : "l"(p));
    return a;
}
__device__ __forceinline__ void cpa16(uint32_t dst, const void* src) {
    asm volatile("cp.async.cg.shared.global [%0], [%1], 16;" :: "r"(dst), "l"(src));
}
#define CPA_COMMIT() asm volatile("cp.async.commit_group;" ::: "memory")
#define CPA_WAIT(n)  asm volatile("cp.async.wait_group %0;" :: "n"(n) : "memory")

// ---------------- x -> bf16 convert ----------------
__global__ void k_cvt(const float* __restrict__ x) {
    int t = blockIdx.x * blockDim.x + threadIdx.x;   // 8 floats per thread
    if (t * 8 < N_NODES * D) {
        float4 v0 = *(const float4*)(x + t * 8);
        float4 v1 = *(const float4*)(x + t * 8 + 4);
        uint4 o;
        o.x = bfpack(v0.x, v0.y);
        o.y = bfpack(v0.z, v0.w);
        o.z = bfpack(v1.x, v1.y);
        o.w = bfpack(v1.z, v1.w);
        *(uint4*)(g_hb + t * 4) = o;
    }
}

// ---------------- CSR build ----------------
#define EDGE_Q (N_EDGES / 4)

__global__ void k_hist(const int* __restrict__ ei) {
    int t = blockIdx.x * blockDim.x + threadIdx.x;
    if (t < EDGE_Q) {
        int d0 = ei[N_EDGES + t];
        int d1 = ei[N_EDGES + t + EDGE_Q];
        int d2 = ei[N_EDGES + t + 2 * EDGE_Q];
        int d3 = ei[N_EDGES + t + 3 * EDGE_Q];
        atomicAdd(&g_deg[d0], 1);
        atomicAdd(&g_deg[d1], 1);
        atomicAdd(&g_deg[d2], 1);
        atomicAdd(&g_deg[d3], 1);
    }
}

__global__ void k_scan() {
    const int ITEMS = 25;
    __shared__ int wsum[32];
    int tid = threadIdx.x;
    int lane = tid & 31, warp = tid >> 5;
    int base = tid * ITEMS;
    int v[ITEMS];
    int s = 0;
    #pragma unroll
    for (int i = 0; i < ITEMS; i++) {
        int idx = base + i;
        v[i] = (idx < N_NODES) ? g_deg[idx] : 0;
        s += v[i];
    }
    int x = s;
    #pragma unroll
    for (int o = 1; o < 32; o <<= 1) {
        int y = __shfl_up_sync(0xFFFFFFFFu, x, o);
        if (lane >= o) x += y;
    }
    if (lane == 31) wsum[warp] = x;
    __syncthreads();
    if (tid < 32) {
        int w = wsum[tid];
        #pragma unroll
        for (int o = 1; o < 32; o <<= 1) {
            int y = __shfl_up_sync(0xFFFFFFFFu, w, o);
            if (tid >= o) w += y;
        }
        wsum[tid] = w;
    }
    __syncthreads();
    int excl = x - s + ((warp > 0) ? wsum[warp - 1] : 0);
    #pragma unroll
    for (int i = 0; i < ITEMS; i++) {
        int idx = base + i;
        if (idx < N_NODES) { g_off[idx] = excl; g_cur[idx] = excl; }
        excl += v[i];
    }
    if (tid == 1023) g_off[N_NODES] = excl;
}

__global__ void k_fill(const int* __restrict__ ei) {
    int t = blockIdx.x * blockDim.x + threadIdx.x;
    if (t < EDGE_Q) {
        #pragma unroll
        for (int i = 0; i < 4; i++) {
            int e = t + i * EDGE_Q;
            int s = ei[e];
            int d = ei[N_EDGES + e];
            int pos = atomicAdd(&g_cur[d], 1);
            g_col[pos] = s;
        }
    }
}

// ---------------- GIN aggregation (bf16 gather, fp32 accumulate) ------------
// one warp per node; lane covers cols [lane*4, lane*4+4) = one uint2 (4 bf16)
__global__ void k_agg(const float* __restrict__ eps, int layer) {
    int gt = blockIdx.x * blockDim.x + threadIdx.x;
    int node = gt >> 5;
    if (node >= N_NODES) return;
    int lane = gt & 31;
    float epsv = 1.0f + eps[layer];
    const uint2* hb = (const uint2*)g_hb;      // 32 uint2 per row
    uint2 sv = hb[(size_t)node * 32 + lane];
    float4 acc;
    acc.x = bflo(sv.x) * epsv; acc.y = bfhi(sv.x) * epsv;
    acc.z = bflo(sv.y) * epsv; acc.w = bfhi(sv.y) * epsv;
    int e = g_off[node], end = g_off[node + 1];
    for (; e + 3 < end; e += 4) {
        int c0 = g_col[e], c1 = g_col[e + 1], c2 = g_col[e + 2], c3 = g_col[e + 3];
        uint2 v0 = hb[(size_t)c0 * 32 + lane];
        uint2 v1 = hb[(size_t)c1 * 32 + lane];
        uint2 v2 = hb[(size_t)c2 * 32 + lane];
        uint2 v3 = hb[(size_t)c3 * 32 + lane];
        acc.x += (bflo(v0.x) + bflo(v1.x)) + (bflo(v2.x) + bflo(v3.x));
        acc.y += (bfhi(v0.x) + bfhi(v1.x)) + (bfhi(v2.x) + bfhi(v3.x));
        acc.z += (bflo(v0.y) + bflo(v1.y)) + (bflo(v2.y) + bflo(v3.y));
        acc.w += (bfhi(v0.y) + bfhi(v1.y)) + (bfhi(v2.y) + bfhi(v3.y));
    }
    for (; e < end; e++) {
        int c = g_col[e];
        uint2 v = hb[(size_t)c * 32 + lane];
        acc.x += bflo(v.x); acc.y += bfhi(v.x);
        acc.z += bflo(v.y); acc.w += bfhi(v.y);
    }
    ((float4*)g_agg)[(size_t)node * 32 + lane] = acc;
}

// ---------------- fused layer: relu( relu(BN(A@W1)) @ W2 + b2 ) ------------
// TILE 192 x 128, 384 threads, occ 1, grid 131 ~ one wave.
// W1/W2 loaded via cp.async; W2's wait deferred until after GEMM1 (hidden).
// LAST=0: write bf16 h -> g_hb ; LAST=1: write fp32 h -> g_h (pool input)
#define FM 192
#define FSTRIDE 129
#define OFF_B1 (FM * FSTRIDE)             // floats
#define OFF_B2 (OFF_B1 + D * D)
#define OFF_CONS (OFF_B2 + D * D)
#define FUSED_SMEM ((OFF_CONS + 384) * 4) // 231680 B

template <int LAST>
__global__ void __launch_bounds__(384, 1) k_fused(
    const float* __restrict__ A, const float* __restrict__ W1,
    const float* __restrict__ W2, int M,
    const float* __restrict__ b1, const float* __restrict__ gamma,
    const float* __restrict__ beta, const float* __restrict__ mean,
    const float* __restrict__ var, const float* __restrict__ b2)
{
    extern __shared__ float sm[];
    float* As   = sm;               // 192 x 129 (A, later z)
    float* B1s  = sm + OFF_B1;
    float* B2s  = sm + OFF_B2;
    float* cons = sm + OFF_CONS;    // s[128], t[128], bias2[128]
    int tid = threadIdx.x;
    int m0 = blockIdx.x * FM;
    uint32_t sb = smem_u32(sm);

    // ---- prologue: async weight loads; W2 completion deferred ----
    {
        const float4* W14 = (const float4*)W1;
        const float4* W24 = (const float4*)W2;
        uint32_t b1dst = sb + OFF_B1 * 4;
        uint32_t b2dst = sb + OFF_B2 * 4;
        #pragma unroll
        for (int i = 0; i < 11; i++) {
            int idx = tid + i * 384;
            if (idx < 4096) cpa16(b1dst + idx * 16, W14 + idx);
        }
        CPA_COMMIT();                      // group: W1
        #pragma unroll
        for (int i = 0; i < 11; i++) {
            int idx = tid + i * 384;
            if (idx < 4096) cpa16(b2dst + idx * 16, W24 + idx);
        }
        CPA_COMMIT();                      // group: W2
        // A tile (plain LDG/STS, padded stride 129)
        #pragma unroll
        for (int i = 0; i < 16; i++) {
            int idx = tid + i * 384;
            int r = idx >> 5, c4 = idx & 31;
            int row = m0 + r;
            float4 v = (row < M) ? *(const float4*)(A + (size_t)row * D + c4 * 4)
                                 : make_float4(0.f, 0.f, 0.f, 0.f);
            float* dst = As + r * FSTRIDE + c4 * 4;
            dst[0] = v.x; dst[1] = v.y; dst[2] = v.z; dst[3] = v.w;
        }
        if (tid < 128) {
            float s = gamma[tid] * rsqrtf(var[tid] + 1e-5f);
            cons[tid]       = s;
            cons[128 + tid] = (b1[tid] - mean[tid]) * s + beta[tid];
            cons[256 + tid] = b2[tid];
        }
    }
    CPA_WAIT(1);                           // W1 landed (W2 may still be in flight)
    __syncthreads();

    int warp = tid >> 5;
    int lane = tid & 31;
    int cg = (warp & 3) * 32;
    int rg = (warp >> 2) * 64;

    ull acc[2][16];
    #pragma unroll
    for (int j = 0; j < 2; j++)
        #pragma unroll
        for (int p = 0; p < 16; p++) acc[j][p] = 0ull;

    const float* a0 = As + (rg + lane) * FSTRIDE;
    const float* a1 = a0 + 32 * FSTRIDE;

    // ---- GEMM1 ----
    {
        const float* bp = B1s + cg;
        #pragma unroll 2
        for (int k = 0; k < D; k++) {
            ull b[16];
            const ulonglong2* br = (const ulonglong2*)(bp + (size_t)k * D);
            #pragma unroll
            for (int q = 0; q < 8; q++) { ulonglong2 t2 = br[q]; b[2*q] = t2.x; b[2*q+1] = t2.y; }
            ull x0 = pack2(a0[k]);
            ull x1 = pack2(a1[k]);
            #pragma unroll
            for (int p = 0; p < 16; p++) {
                fma2(acc[0][p], x0, b[p], acc[0][p]);
                fma2(acc[1][p], x1, b[p], acc[1][p]);
            }
        }
    }

    // ---- BN + ReLU -> z into As ----
    CPA_WAIT(0);              // W2 landed
    __syncthreads();          // all reads of A done; W2 visible block-wide
    #pragma unroll
    for (int j = 0; j < 2; j++) {
        float* zr = As + (rg + lane + 32 * j) * FSTRIDE + cg;
        #pragma unroll
        for (int p = 0; p < 16; p++) {
            float2 v = unpack2(acc[j][p]);
            int c = 2 * p;
            zr[c]     = fmaxf(fmaf(v.x, cons[cg + c],     cons[128 + cg + c]),     0.f);
            zr[c + 1] = fmaxf(fmaf(v.y, cons[cg + c + 1], cons[128 + cg + c + 1]), 0.f);
        }
    }
    __syncthreads();

    // ---- GEMM2 ----
    #pragma unroll
    for (int j = 0; j < 2; j++)
        #pragma unroll
        for (int p = 0; p < 16; p++) acc[j][p] = 0ull;
    {
        const float* bp = B2s + cg;
        #pragma unroll 2
        for (int k = 0; k < D; k++) {
            ull b[16];
            const ulonglong2* br = (const ulonglong2*)(bp + (size_t)k * D);
            #pragma unroll
            for (int q = 0; q < 8; q++) { ulonglong2 t2 = br[q]; b[2*q] = t2.x; b[2*q+1] = t2.y; }
            ull x0 = pack2(a0[k]);
            ull x1 = pack2(a1[k]);
            #pragma unroll
            for (int p = 0; p < 16; p++) {
                fma2(acc[0][p], x0, b[p], acc[0][p]);
                fma2(acc[1][p], x1, b[p], acc[1][p]);
            }
        }
    }

    // ---- bias + ReLU -> output ----
    #pragma unroll
    for (int j = 0; j < 2; j++) {
        int row = m0 + rg + lane + 32 * j;
        if (row < M) {
            float o[32];
            #pragma unroll
            for (int p = 0; p < 16; p++) {
                float2 v = unpack2(acc[j][p]);
                o[2*p]     = fmaxf(v.x + cons[256 + cg + 2*p],     0.f);
                o[2*p + 1] = fmaxf(v.y + cons[256 + cg + 2*p + 1], 0.f);
            }
            if (LAST) {
                float* cp = g_h + (size_t)row * D + cg;
                #pragma unroll
                for (int q = 0; q < 8; q++)
                    *(float4*)(cp + 4*q) = make_float4(o[4*q], o[4*q+1], o[4*q+2], o[4*q+3]);
            } else {
                unsigned* hp = g_hb + (size_t)row * 64 + cg / 2;
                #pragma unroll
                for (int q = 0; q < 4; q++) {
                    uint4 w;
                    w.x = bfpack(o[8*q],     o[8*q + 1]);
                    w.y = bfpack(o[8*q + 2], o[8*q + 3]);
                    w.z = bfpack(o[8*q + 4], o[8*q + 5]);
                    w.w = bfpack(o[8*q + 6], o[8*q + 7]);
                    *(uint4*)(hp + 4*q) = w;
                }
            }
        }
    }
}

// ---------------- mean-pool per graph + final linear ----------------
__global__ void k_pool(const float* __restrict__ h, const int* __restrict__ batch,
                       const float* __restrict__ Wout, const float* __restrict__ bout,
                       float* __restrict__ out)
{
    int g = blockIdx.x;
    int t = threadIdx.x;   // 128

    int lo = 0, hi = N_NODES;
    while (lo < hi) { int mid = (lo + hi) >> 1; if (batch[mid] < g) lo = mid + 1; else hi = mid; }
    int start = lo;
    lo = start; hi = N_NODES;
    while (lo < hi) { int mid = (lo + hi) >> 1; if (batch[mid] < g + 1) lo = mid + 1; else hi = mid; }
    int stop = lo;

    float s = 0.f;
    for (int n = start; n < stop; n++) s += h[(size_t)n * D + t];
    float cnt = fmaxf((float)(stop - start), 1.f);

    __shared__ float sp[D];
    sp[t] = s / cnt;
    __syncthreads();

    if (t < D_OUT) {
        float acc = bout[t];
        #pragma unroll 8
        for (int k = 0; k < D; k++) acc += sp[k] * Wout[k * D_OUT + t];
        out[g * D_OUT + t] = acc;
    }
}

// ---------------- host launcher ----------------
extern "C" void kernel_launch(void* const* d_in, const int* in_sizes, int n_in,
                              void* d_out, int out_size)
{
    const float* x     = (const float*)d_in[0];
    const int*   ei    = (const int*)d_in[1];
    const int*   batch = (const int*)d_in[2];
    const float* W1    = (const float*)d_in[3];
    const float* b1    = (const float*)d_in[4];
    const float* gamma = (const float*)d_in[5];
    const float* beta  = (const float*)d_in[6];
    const float* rmean = (const float*)d_in[7];
    const float* rvar  = (const float*)d_in[8];
    const float* W2    = (const float*)d_in[9];
    const float* b2    = (const float*)d_in[10];
    const float* eps   = (const float*)d_in[11];
    const float* Wout  = (const float*)d_in[12];
    const float* bout  = (const float*)d_in[13];
    float* out = (float*)d_out;

    float* p_h;
    int* p_deg;
    cudaGetSymbolAddress((void**)&p_h,   g_h);
    cudaGetSymbolAddress((void**)&p_deg, g_deg);
    float* p_agg;
    cudaGetSymbolAddress((void**)&p_agg, g_agg);

    cudaFuncSetAttribute(k_fused<0>, cudaFuncAttributeMaxDynamicSharedMemorySize, FUSED_SMEM);
    cudaFuncSetAttribute(k_fused<1>, cudaFuncAttributeMaxDynamicSharedMemorySize, FUSED_SMEM);

    // ---- CSR build + x->bf16 (deterministic every call) ----
    cudaMemsetAsync(p_deg, 0, N_NODES * sizeof(int));
    k_cvt<<<(N_NODES * D / 8 + 255) / 256, 256>>>(x);
    k_hist<<<(EDGE_Q + 255) / 256, 256>>>(ei);
    k_scan<<<1, 1024>>>();
    k_fill<<<(EDGE_Q + 255) / 256, 256>>>(ei);

    const int fused_blocks = (N_NODES + FM - 1) / FM;    // 131
    const int agg_blocks   = (N_NODES * 32 + 255) / 256;

    for (int l = 0; l < N_LAYERS; l++) {
        k_agg<<<agg_blocks, 256>>>(eps, l);
        if (l < N_LAYERS - 1) {
            k_fused<0><<<fused_blocks, 384, FUSED_SMEM>>>(
                p_agg, W1 + (size_t)l * D * D, W2 + (size_t)l * D * D, N_NODES,
                b1 + l * D, gamma + l * D, beta + l * D, rmean + l * D, rvar + l * D,
                b2 + l * D);
        } else {
            k_fused<1><<<fused_blocks, 384, FUSED_SMEM>>>(
                p_agg, W1 + (size_t)l * D * D, W2 + (size_t)l * D * D, N_NODES,
                b1 + l * D, gamma + l * D, beta + l * D, rmean + l * D, rvar + l * D,
                b2 + l * D);
        }
    }

    k_pool<<<N_GRAPHS, D>>>(p_h, batch, Wout, bout, out);
}

// round 11
// speedup vs baseline: 2.5685x; 1.6385x over previous
#include <cuda_runtime.h>
#include <cstdint>

#define N_NODES 25000
#define N_EDGES 400000
#define D       128
#define N_LAYERS 3
#define N_GRAPHS 512
#define D_OUT   10

typedef unsigned int uint;

// ---------------- device scratch ----------------
__device__ float    g_h[N_NODES * D];            // fp32 h3 (pool input)
__device__ unsigned g_hb[N_NODES * D / 2];       // bf16x2 h (agg input)
__device__ unsigned g_aggb[N_NODES * D / 2];     // bf16x2 agg (GEMM1 A input)
__device__ unsigned g_whi[N_LAYERS][2][128 * 68]; // bf16x2 W hi, padded pitch 136
__device__ unsigned g_wlo[N_LAYERS][2][128 * 68]; // bf16x2 W lo
__device__ int      g_deg[N_NODES];
__device__ int      g_off[N_NODES + 1];
__device__ int      g_cur[N_NODES];
__device__ int      g_col[N_EDGES];

// ---------------- helpers ----------
__device__ __forceinline__ unsigned bfpack(float e0, float e1) {
    unsigned r;   // low half = bf16(e0), high half = bf16(e1)
    asm("cvt.rn.bf16x2.f32 %0, %1, %2;" : "=r"(r) : "f"(e1), "f"(e0));
    return r;
}
__device__ __forceinline__ float bflo(unsigned p) { return __uint_as_float(p << 16); }
__device__ __forceinline__ float bfhi(unsigned p) { return __uint_as_float(p & 0xFFFF0000u); }

__device__ __forceinline__ uint32_t smem_u32(const void* p) {
    uint32_t a;
    asm("{ .reg .u64 t; cvta.to.shared.u64 t, %1; cvt.u32.u64 %0, t; }" : "=r"(a) : "l"(p));
    return a;
}
__device__ __forceinline__ void cpa16(uint32_t dst, const void* src) {
    asm volatile("cp.async.cg.shared.global [%0], [%1], 16;" :: "r"(dst), "l"(src));
}
#define CPA_COMMIT() asm volatile("cp.async.commit_group;" ::: "memory")
#define CPA_WAIT(n)  asm volatile("cp.async.wait_group %0;" :: "n"(n) : "memory")

__device__ __forceinline__ void ldsm4(uint* r, uint32_t addr) {
    asm volatile("ldmatrix.sync.aligned.m8n8.x4.shared.b16 {%0,%1,%2,%3}, [%4];"
                 : "=r"(r[0]), "=r"(r[1]), "=r"(r[2]), "=r"(r[3]) : "r"(addr));
}
__device__ __forceinline__ void ldsm4t(uint* r, uint32_t addr) {
    asm volatile("ldmatrix.sync.aligned.m8n8.x4.trans.shared.b16 {%0,%1,%2,%3}, [%4];"
                 : "=r"(r[0]), "=r"(r[1]), "=r"(r[2]), "=r"(r[3]) : "r"(addr));
}
__device__ __forceinline__ void mma16816(float* c, const uint* a, const uint* b) {
    asm volatile(
        "mma.sync.aligned.m16n8k16.row.col.f32.bf16.bf16.f32 "
        "{%0,%1,%2,%3}, {%4,%5,%6,%7}, {%8,%9}, {%0,%1,%2,%3};"
        : "+f"(c[0]), "+f"(c[1]), "+f"(c[2]), "+f"(c[3])
        : "r"(a[0]), "r"(a[1]), "r"(a[2]), "r"(a[3]), "r"(b[0]), "r"(b[1]));
}

// ---------------- x -> bf16 ----------------
__global__ void k_cvt(const float* __restrict__ x) {
    int t = blockIdx.x * blockDim.x + threadIdx.x;
    if (t * 8 < N_NODES * D) {
        float4 v0 = *(const float4*)(x + t * 8);
        float4 v1 = *(const float4*)(x + t * 8 + 4);
        uint4 o;
        o.x = bfpack(v0.x, v0.y);
        o.y = bfpack(v0.z, v0.w);
        o.z = bfpack(v1.x, v1.y);
        o.w = bfpack(v1.z, v1.w);
        *(uint4*)(g_hb + t * 4) = o;
    }
}

// ---------------- W -> hi/lo bf16 split, padded pitch 136 ----------------
__global__ void k_wcvt(const float* __restrict__ W1, const float* __restrict__ W2) {
    int t = blockIdx.x * blockDim.x + threadIdx.x;   // one col-pair per thread
    if (t >= 3 * 2 * 128 * 64) return;
    int e2 = t & 63;             // col pair: cols 2*e2, 2*e2+1
    int r  = (t >> 6) & 127;
    int m  = t >> 13;            // 0..5
    int l = m >> 1, j = m & 1;
    const float* src = (j ? W2 : W1) + (size_t)l * 16384 + r * 128 + e2 * 2;
    float v0 = src[0], v1 = src[1];
    unsigned hi = bfpack(v0, v1);
    float l0 = v0 - bflo(hi);
    float l1 = v1 - bfhi(hi);
    unsigned lo = bfpack(l0, l1);
    int idx = r * 68 + e2;
    g_whi[l][j][idx] = hi;
    g_wlo[l][j][idx] = lo;
}

// ---------------- CSR build ----------------
#define EDGE_Q (N_EDGES / 4)

__global__ void k_hist(const int* __restrict__ ei) {
    int t = blockIdx.x * blockDim.x + threadIdx.x;
    if (t < EDGE_Q) {
        int d0 = ei[N_EDGES + t];
        int d1 = ei[N_EDGES + t + EDGE_Q];
        int d2 = ei[N_EDGES + t + 2 * EDGE_Q];
        int d3 = ei[N_EDGES + t + 3 * EDGE_Q];
        atomicAdd(&g_deg[d0], 1);
        atomicAdd(&g_deg[d1], 1);
        atomicAdd(&g_deg[d2], 1);
        atomicAdd(&g_deg[d3], 1);
    }
}

__global__ void k_scan() {
    const int ITEMS = 25;
    __shared__ int wsum[32];
    int tid = threadIdx.x;
    int lane = tid & 31, warp = tid >> 5;
    int base = tid * ITEMS;
    int v[ITEMS];
    int s = 0;
    #pragma unroll
    for (int i = 0; i < ITEMS; i++) {
        int idx = base + i;
        v[i] = (idx < N_NODES) ? g_deg[idx] : 0;
        s += v[i];
    }
    int x = s;
    #pragma unroll
    for (int o = 1; o < 32; o <<= 1) {
        int y = __shfl_up_sync(0xFFFFFFFFu, x, o);
        if (lane >= o) x += y;
    }
    if (lane == 31) wsum[warp] = x;
    __syncthreads();
    if (tid < 32) {
        int w = wsum[tid];
        #pragma unroll
        for (int o = 1; o < 32; o <<= 1) {
            int y = __shfl_up_sync(0xFFFFFFFFu, w, o);
            if (tid >= o) w += y;
        }
        wsum[tid] = w;
    }
    __syncthreads();
    int excl = x - s + ((warp > 0) ? wsum[warp - 1] : 0);
    #pragma unroll
    for (int i = 0; i < ITEMS; i++) {
        int idx = base + i;
        if (idx < N_NODES) { g_off[idx] = excl; g_cur[idx] = excl; }
        excl += v[i];
    }
    if (tid == 1023) g_off[N_NODES] = excl;
}

__global__ void k_fill(const int* __restrict__ ei) {
    int t = blockIdx.x * blockDim.x + threadIdx.x;
    if (t < EDGE_Q) {
        #pragma unroll
        for (int i = 0; i < 4; i++) {
            int e = t + i * EDGE_Q;
            int s = ei[e];
            int d = ei[N_EDGES + e];
            int pos = atomicAdd(&g_cur[d], 1);
            g_col[pos] = s;
        }
    }
}

// ---------------- GIN aggregation (bf16 in, fp32 acc, bf16 out) ----------
__global__ void k_agg(const float* __restrict__ eps, int layer) {
    int gt = blockIdx.x * blockDim.x + threadIdx.x;
    int node = gt >> 5;
    if (node >= N_NODES) return;
    int lane = gt & 31;
    float epsv = 1.0f + eps[layer];
    const uint2* hb = (const uint2*)g_hb;
    uint2 sv = hb[(size_t)node * 32 + lane];
    float4 acc;
    acc.x = bflo(sv.x) * epsv; acc.y = bfhi(sv.x) * epsv;
    acc.z = bflo(sv.y) * epsv; acc.w = bfhi(sv.y) * epsv;
    int e = g_off[node], end = g_off[node + 1];
    for (; e + 3 < end; e += 4) {
        int c0 = g_col[e], c1 = g_col[e + 1], c2 = g_col[e + 2], c3 = g_col[e + 3];
        uint2 v0 = hb[(size_t)c0 * 32 + lane];
        uint2 v1 = hb[(size_t)c1 * 32 + lane];
        uint2 v2 = hb[(size_t)c2 * 32 + lane];
        uint2 v3 = hb[(size_t)c3 * 32 + lane];
        acc.x += (bflo(v0.x) + bflo(v1.x)) + (bflo(v2.x) + bflo(v3.x));
        acc.y += (bfhi(v0.x) + bfhi(v1.x)) + (bfhi(v2.x) + bfhi(v3.x));
        acc.z += (bflo(v0.y) + bflo(v1.y)) + (bflo(v2.y) + bflo(v3.y));
        acc.w += (bfhi(v0.y) + bfhi(v1.y)) + (bfhi(v2.y) + bfhi(v3.y));
    }
    for (; e < end; e++) {
        int c = g_col[e];
        uint2 v = hb[(size_t)c * 32 + lane];
        acc.x += bflo(v.x); acc.y += bfhi(v.x);
        acc.z += bflo(v.y); acc.w += bfhi(v.y);
    }
    uint2 o;
    o.x = bfpack(acc.x, acc.y);
    o.y = bfpack(acc.z, acc.w);
    ((uint2*)g_aggb)[(size_t)node * 32 + lane] = o;
}

// ---------------- fused layer via mma.sync (HMMA bf16, f32 acc) ----------
// TILE 192 x 128, 384 threads (12 warps), warp tile 32x64. Grid 131 = 1 wave.
// A (bf16, pitch 136), W1/W2 hi+lo (bf16, pitch 136, cp.async'd pre-split).
// z = relu(BN(A@W1)) overwrites A in smem; out = relu(z@W2 + b2).
#define FM 192
#define APITCHB 272                 // bytes per A/W row (136 bf16)
#define OFF_W1H 52224               // 192*272
#define OFF_W1L (OFF_W1H + 34816)   // 128*272
#define OFF_W2H (OFF_W1L + 34816)
#define OFF_W2L (OFF_W2H + 34816)
#define OFF_CONS (OFF_W2L + 34816)  // 191488
#define FUSED_SMEM (OFF_CONS + 1536)

__device__ __forceinline__ void gemm_tile(
    uint32_t aB0, uint32_t aB1, uint32_t wHiB, uint32_t wLoB, float acc[2][8][4])
{
    #pragma unroll
    for (int k0 = 0; k0 < 128; k0 += 16) {
        uint a0[4], a1[4];
        ldsm4(a0, aB0 + k0 * 2);
        ldsm4(a1, aB1 + k0 * 2);
        #pragma unroll
        for (int np = 0; np < 4; np++) {
            uint b[4];
            ldsm4t(b, wHiB + k0 * APITCHB + np * 32);
            mma16816(acc[0][2*np],     a0, b);
            mma16816(acc[0][2*np + 1], a0, b + 2);
            mma16816(acc[1][2*np],     a1, b);
            mma16816(acc[1][2*np + 1], a1, b + 2);
            ldsm4t(b, wLoB + k0 * APITCHB + np * 32);
            mma16816(acc[0][2*np],     a0, b);
            mma16816(acc[0][2*np + 1], a0, b + 2);
            mma16816(acc[1][2*np],     a1, b);
            mma16816(acc[1][2*np + 1], a1, b + 2);
        }
    }
}

template <int LAST>
__global__ void __launch_bounds__(384, 1) k_fused(
    int layer, int M,
    const float* __restrict__ b1, const float* __restrict__ gamma,
    const float* __restrict__ beta, const float* __restrict__ mean,
    const float* __restrict__ var, const float* __restrict__ b2)
{
    extern __shared__ char sm[];
    float* cons = (float*)(sm + OFF_CONS);
    int tid = threadIdx.x;
    int m0 = blockIdx.x * FM;
    uint32_t sb = smem_u32(sm);

    // ---- weights via cp.async: group0 = W1 hi+lo, group1 = W2 hi+lo ----
    {
        const char* w1h = (const char*)g_whi[layer][0];
        const char* w1l = (const char*)g_wlo[layer][0];
        const char* w2h = (const char*)g_whi[layer][1];
        const char* w2l = (const char*)g_wlo[layer][1];
        for (int i = tid; i < 2176; i += 384) {
            cpa16(sb + OFF_W1H + i * 16, w1h + i * 16);
            cpa16(sb + OFF_W1L + i * 16, w1l + i * 16);
        }
        CPA_COMMIT();
        for (int i = tid; i < 2176; i += 384) {
            cpa16(sb + OFF_W2H + i * 16, w2h + i * 16);
            cpa16(sb + OFF_W2L + i * 16, w2l + i * 16);
        }
        CPA_COMMIT();
    }
    // ---- A tile: bf16 from g_aggb, 16B chunks, padded pitch ----
    {
        #pragma unroll
        for (int i = 0; i < 8; i++) {
            int idx = tid + i * 384;          // 0..3071
            int r = idx >> 4, c16 = idx & 15;
            int row = m0 + r;
            uint4 v = (row < M) ? *(const uint4*)(g_aggb + (size_t)row * 64 + c16 * 4)
                                : make_uint4(0, 0, 0, 0);
            *(uint4*)(sm + r * APITCHB + c16 * 16) = v;
        }
        if (tid < 128) {
            float s = gamma[tid] * rsqrtf(var[tid] + 1e-5f);
            cons[tid]       = s;
            cons[128 + tid] = (b1[tid] - mean[tid]) * s + beta[tid];
            cons[256 + tid] = b2[tid];
        }
    }
    CPA_WAIT(1);           // W1 hi/lo landed
    __syncthreads();

    int warp = tid >> 5;
    int lane = tid & 31;
    int mBase = (warp % 6) * 32;
    int nBase = (warp / 6) * 64;
    int lr  = lane & 15;               // ldmatrix row-within-16
    int lc8 = (lane >> 4) << 3;        // 0 or 8
    int g = lane >> 2, t = lane & 3;

    uint32_t aB0 = sb + (mBase + lr) * APITCHB + lc8 * 2;
    uint32_t aB1 = aB0 + 16 * APITCHB;
    uint32_t wRow = lr * APITCHB + (nBase + lc8) * 2;

    float acc[2][8][4];
    #pragma unroll
    for (int mt = 0; mt < 2; mt++)
        #pragma unroll
        for (int ng = 0; ng < 8; ng++)
            #pragma unroll
            for (int i = 0; i < 4; i++) acc[mt][ng][i] = 0.f;

    // ---- GEMM1 ----
    gemm_tile(aB0, aB1, sb + OFF_W1H + wRow, sb + OFF_W1L + wRow, acc);

    // ---- BN + ReLU -> z overwrites A ----
    CPA_WAIT(0);           // W2 hi/lo landed
    __syncthreads();       // all A reads complete
    #pragma unroll
    for (int mt = 0; mt < 2; mt++) {
        int r0 = mBase + mt * 16 + g;
        #pragma unroll
        for (int ng = 0; ng < 8; ng++) {
            int colL = nBase + ng * 8 + 2 * t;
            float s0 = cons[colL], s1 = cons[colL + 1];
            float t0 = cons[128 + colL], t1 = cons[128 + colL + 1];
            float z00 = fmaxf(fmaf(acc[mt][ng][0], s0, t0), 0.f);
            float z01 = fmaxf(fmaf(acc[mt][ng][1], s1, t1), 0.f);
            float z10 = fmaxf(fmaf(acc[mt][ng][2], s0, t0), 0.f);
            float z11 = fmaxf(fmaf(acc[mt][ng][3], s1, t1), 0.f);
            *(uint*)(sm + r0 * APITCHB + colL * 2)       = bfpack(z00, z01);
            *(uint*)(sm + (r0 + 8) * APITCHB + colL * 2) = bfpack(z10, z11);
        }
    }
    __syncthreads();

    // ---- GEMM2 ----
    #pragma unroll
    for (int mt = 0; mt < 2; mt++)
        #pragma unroll
        for (int ng = 0; ng < 8; ng++)
            #pragma unroll
            for (int i = 0; i < 4; i++) acc[mt][ng][i] = 0.f;
    gemm_tile(aB0, aB1, sb + OFF_W2H + wRow, sb + OFF_W2L + wRow, acc);

    // ---- bias + ReLU -> output ----
    #pragma unroll
    for (int mt = 0; mt < 2; mt++) {
        int r0 = m0 + mBase + mt * 16 + g;
        #pragma unroll
        for (int ng = 0; ng < 8; ng++) {
            int colL = nBase + ng * 8 + 2 * t;
            float bb0 = cons[256 + colL], bb1 = cons[256 + colL + 1];
            float o00 = fmaxf(acc[mt][ng][0] + bb0, 0.f);
            float o01 = fmaxf(acc[mt][ng][1] + bb1, 0.f);
            float o10 = fmaxf(acc[mt][ng][2] + bb0, 0.f);
            float o11 = fmaxf(acc[mt][ng][3] + bb1, 0.f);
            if (LAST) {
                if (r0 < M)     *(float2*)(g_h + (size_t)r0 * D + colL)       = make_float2(o00, o01);
                if (r0 + 8 < M) *(float2*)(g_h + (size_t)(r0 + 8) * D + colL) = make_float2(o10, o11);
            } else {
                if (r0 < M)     g_hb[(size_t)r0 * 64 + colL / 2]       = bfpack(o00, o01);
                if (r0 + 8 < M) g_hb[(size_t)(r0 + 8) * 64 + colL / 2] = bfpack(o10, o11);
            }
        }
    }
}

// ---------------- mean-pool per graph + final linear ----------------
__global__ void k_pool(const float* __restrict__ h, const int* __restrict__ batch,
                       const float* __restrict__ Wout, const float* __restrict__ bout,
                       float* __restrict__ out)
{
    int g = blockIdx.x;
    int t = threadIdx.x;   // 128

    int lo = 0, hi = N_NODES;
    while (lo < hi) { int mid = (lo + hi) >> 1; if (batch[mid] < g) lo = mid + 1; else hi = mid; }
    int start = lo;
    lo = start; hi = N_NODES;
    while (lo < hi) { int mid = (lo + hi) >> 1; if (batch[mid] < g + 1) lo = mid + 1; else hi = mid; }
    int stop = lo;

    float s = 0.f;
    for (int n = start; n < stop; n++) s += h[(size_t)n * D + t];
    float cnt = fmaxf((float)(stop - start), 1.f);

    __shared__ float sp[D];
    sp[t] = s / cnt;
    __syncthreads();

    if (t < D_OUT) {
        float acc = bout[t];
        #pragma unroll 8
        for (int k = 0; k < D; k++) acc += sp[k] * Wout[k * D_OUT + t];
        out[g * D_OUT + t] = acc;
    }
}

// ---------------- host launcher ----------------
extern "C" void kernel_launch(void* const* d_in, const int* in_sizes, int n_in,
                              void* d_out, int out_size)
{
    const float* x     = (const float*)d_in[0];
    const int*   ei    = (const int*)d_in[1];
    const int*   batch = (const int*)d_in[2];
    const float* W1    = (const float*)d_in[3];
    const float* b1    = (const float*)d_in[4];
    const float* gamma = (const float*)d_in[5];
    const float* beta  = (const float*)d_in[6];
    const float* rmean = (const float*)d_in[7];
    const float* rvar  = (const float*)d_in[8];
    const float* W2    = (const float*)d_in[9];
    const float* b2    = (const float*)d_in[10];
    const float* eps   = (const float*)d_in[11];
    const float* Wout  = (const float*)d_in[12];
    const float* bout  = (const float*)d_in[13];
    float* out = (float*)d_out;

    float* p_h;
    int* p_deg;
    cudaGetSymbolAddress((void**)&p_h,   g_h);
    cudaGetSymbolAddress((void**)&p_deg, g_deg);

    cudaFuncSetAttribute(k_fused<0>, cudaFuncAttributeMaxDynamicSharedMemorySize, FUSED_SMEM);
    cudaFuncSetAttribute(k_fused<1>, cudaFuncAttributeMaxDynamicSharedMemorySize, FUSED_SMEM);

    // ---- prep (deterministic every call) ----
    cudaMemsetAsync(p_deg, 0, N_NODES * sizeof(int));
    k_cvt<<<(N_NODES * D / 8 + 255) / 256, 256>>>(x);
    k_wcvt<<<(3 * 2 * 128 * 64 + 255) / 256, 256>>>(W1, W2);
    k_hist<<<(EDGE_Q + 255) / 256, 256>>>(ei);
    k_scan<<<1, 1024>>>();
    k_fill<<<(EDGE_Q + 255) / 256, 256>>>(ei);

    const int fused_blocks = (N_NODES + FM - 1) / FM;    // 131
    const int agg_blocks   = (N_NODES * 32 + 255) / 256;

    for (int l = 0; l < N_LAYERS; l++) {
        k_agg<<<agg_blocks, 256>>>(eps, l);
        if (l < N_LAYERS - 1) {
            k_fused<0><<<fused_blocks, 384, FUSED_SMEM>>>(
                l, N_NODES, b1 + l * D, gamma + l * D, beta + l * D,
                rmean + l * D, rvar + l * D, b2 + l * D);
        } else {
            k_fused<1><<<fused_blocks, 384, FUSED_SMEM>>>(
                l, N_NODES, b1 + l * D, gamma + l * D, beta + l * D,
                rmean + l * D, rvar + l * D, b2 + l * D);
        }
    }

    k_pool<<<N_GRAPHS, D>>>(p_h, batch, Wout, bout, out);
}

// round 12
// speedup vs baseline: 3.1585x; 1.2297x over previous
#include <cuda_runtime.h>
#include <cstdint>

#define N_NODES 25000
#define N_EDGES 400000
#define D       128
#define N_LAYERS 3
#define N_GRAPHS 512
#define D_OUT   10

typedef unsigned int uint;

// ---------------- device scratch ----------------
__device__ float    g_h[N_NODES * D];            // fp32 h3 (pool input)
__device__ unsigned g_hb[N_NODES * D / 2];       // bf16x2 h (agg input)
__device__ unsigned g_aggb[N_NODES * D / 2];     // bf16x2 agg (GEMM1 A input)
__device__ unsigned g_whi[N_LAYERS][2][128 * 68]; // bf16x2 W hi, padded pitch 136
__device__ unsigned g_wlo[N_LAYERS][2][128 * 68]; // bf16x2 W lo
__device__ int      g_deg[N_NODES];
__device__ int      g_off[N_NODES + 1];
__device__ int      g_cur[N_NODES];
__device__ int      g_col[N_EDGES];
__device__ int      g_bsum[32];

// ---------------- helpers ----------
__device__ __forceinline__ unsigned bfpack(float e0, float e1) {
    unsigned r;   // low half = bf16(e0), high half = bf16(e1)
    asm("cvt.rn.bf16x2.f32 %0, %1, %2;" : "=r"(r) : "f"(e1), "f"(e0));
    return r;
}
__device__ __forceinline__ float bflo(unsigned p) { return __uint_as_float(p << 16); }
__device__ __forceinline__ float bfhi(unsigned p) { return __uint_as_float(p & 0xFFFF0000u); }

__device__ __forceinline__ uint32_t smem_u32(const void* p) {
    uint32_t a;
    asm("{ .reg .u64 t; cvta.to.shared.u64 t, %1; cvt.u32.u64 %0, t; }" : "=r"(a) : "l"(p));
    return a;
}
__device__ __forceinline__ void cpa16(uint32_t dst, const void* src) {
    asm volatile("cp.async.cg.shared.global [%0], [%1], 16;" :: "r"(dst), "l"(src));
}
#define CPA_COMMIT() asm volatile("cp.async.commit_group;" ::: "memory")
#define CPA_WAIT(n)  asm volatile("cp.async.wait_group %0;" :: "n"(n) : "memory")

__device__ __forceinline__ void ldsm4(uint* r, uint32_t addr) {
    asm volatile("ldmatrix.sync.aligned.m8n8.x4.shared.b16 {%0,%1,%2,%3}, [%4];"
                 : "=r"(r[0]), "=r"(r[1]), "=r"(r[2]), "=r"(r[3]) : "r"(addr));
}
__device__ __forceinline__ void ldsm4t(uint* r, uint32_t addr) {
    asm volatile("ldmatrix.sync.aligned.m8n8.x4.trans.shared.b16 {%0,%1,%2,%3}, [%4];"
                 : "=r"(r[0]), "=r"(r[1]), "=r"(r[2]), "=r"(r[3]) : "r"(addr));
}
__device__ __forceinline__ void mma16816(float* c, const uint* a, const uint* b) {
    asm volatile(
        "mma.sync.aligned.m16n8k16.row.col.f32.bf16.bf16.f32 "
        "{%0,%1,%2,%3}, {%4,%5,%6,%7}, {%8,%9}, {%0,%1,%2,%3};"
        : "+f"(c[0]), "+f"(c[1]), "+f"(c[2]), "+f"(c[3])
        : "r"(a[0]), "r"(a[1]), "r"(a[2]), "r"(a[3]), "r"(b[0]), "r"(b[1]));
}

// ---------------- x -> bf16 ----------------
__global__ void k_cvt(const float* __restrict__ x) {
    int t = blockIdx.x * blockDim.x + threadIdx.x;
    if (t * 8 < N_NODES * D) {
        float4 v0 = *(const float4*)(x + t * 8);
        float4 v1 = *(const float4*)(x + t * 8 + 4);
        uint4 o;
        o.x = bfpack(v0.x, v0.y);
        o.y = bfpack(v0.z, v0.w);
        o.z = bfpack(v1.x, v1.y);
        o.w = bfpack(v1.z, v1.w);
        *(uint4*)(g_hb + t * 4) = o;
    }
}

// ---------------- W -> hi/lo bf16 split, padded pitch 136 ----------------
__global__ void k_wcvt(const float* __restrict__ W1, const float* __restrict__ W2) {
    int t = blockIdx.x * blockDim.x + threadIdx.x;   // one col-pair per thread
    if (t >= 3 * 2 * 128 * 64) return;
    int e2 = t & 63;             // col pair: cols 2*e2, 2*e2+1
    int r  = (t >> 6) & 127;
    int m  = t >> 13;            // 0..5
    int l = m >> 1, j = m & 1;
    const float* src = (j ? W2 : W1) + (size_t)l * 16384 + r * 128 + e2 * 2;
    float v0 = src[0], v1 = src[1];
    unsigned hi = bfpack(v0, v1);
    float l0 = v0 - bflo(hi);
    float l1 = v1 - bfhi(hi);
    unsigned lo = bfpack(l0, l1);
    int idx = r * 68 + e2;
    g_whi[l][j][idx] = hi;
    g_wlo[l][j][idx] = lo;
}

// ---------------- CSR build ----------------
#define EDGE_Q (N_EDGES / 4)
#define SCAN_BLOCKS 25

__global__ void k_hist(const int* __restrict__ ei) {
    int t = blockIdx.x * blockDim.x + threadIdx.x;
    if (t < EDGE_Q) {
        int d0 = ei[N_EDGES + t];
        int d1 = ei[N_EDGES + t + EDGE_Q];
        int d2 = ei[N_EDGES + t + 2 * EDGE_Q];
        int d3 = ei[N_EDGES + t + 3 * EDGE_Q];
        atomicAdd(&g_deg[d0], 1);
        atomicAdd(&g_deg[d1], 1);
        atomicAdd(&g_deg[d2], 1);
        atomicAdd(&g_deg[d3], 1);
    }
}

// phase A: per-block sum of 1024 degrees -> g_bsum
__global__ void k_scan_a() {
    __shared__ int ws[32];
    int i = blockIdx.x * 1024 + threadIdx.x;
    int v = (i < N_NODES) ? g_deg[i] : 0;
    int lane = threadIdx.x & 31, warp = threadIdx.x >> 5;
    #pragma unroll
    for (int o = 16; o; o >>= 1) v += __shfl_down_sync(0xFFFFFFFFu, v, o);
    if (lane == 0) ws[warp] = v;
    __syncthreads();
    if (warp == 0) {
        int s = ws[lane];
        #pragma unroll
        for (int o = 16; o; o >>= 1) s += __shfl_down_sync(0xFFFFFFFFu, s, o);
        if (lane == 0) g_bsum[blockIdx.x] = s;
    }
}
// phase B: one warp scans block sums (exclusive), writes total
__global__ void k_scan_b() {
    int t = threadIdx.x;
    int v = (t < SCAN_BLOCKS) ? g_bsum[t] : 0;
    int x = v;
    #pragma unroll
    for (int o = 1; o < 32; o <<= 1) {
        int y = __shfl_up_sync(0xFFFFFFFFu, x, o);
        if (t >= o) x += y;
    }
    if (t < SCAN_BLOCKS) g_bsum[t] = x - v;
    if (t == SCAN_BLOCKS - 1) g_off[N_NODES] = x;
}
// phase C: per-block exclusive scan + block offset -> g_off, g_cur
__global__ void k_scan_c() {
    __shared__ int ws[32];
    int i = blockIdx.x * 1024 + threadIdx.x;
    int v = (i < N_NODES) ? g_deg[i] : 0;
    int lane = threadIdx.x & 31, warp = threadIdx.x >> 5;
    int x = v;
    #pragma unroll
    for (int o = 1; o < 32; o <<= 1) {
        int y = __shfl_up_sync(0xFFFFFFFFu, x, o);
        if (lane >= o) x += y;
    }
    if (lane == 31) ws[warp] = x;
    __syncthreads();
    if (warp == 0) {
        int w = ws[lane];
        #pragma unroll
        for (int o = 1; o < 32; o <<= 1) {
            int y = __shfl_up_sync(0xFFFFFFFFu, w, o);
            if (lane >= o) w += y;
        }
        ws[lane] = w;
    }
    __syncthreads();
    int excl = x - v + ((warp > 0) ? ws[warp - 1] : 0) + g_bsum[blockIdx.x];
    if (i < N_NODES) { g_off[i] = excl; g_cur[i] = excl; }
}

__global__ void k_fill(const int* __restrict__ ei) {
    int t = blockIdx.x * blockDim.x + threadIdx.x;
    if (t < EDGE_Q) {
        #pragma unroll
        for (int i = 0; i < 4; i++) {
            int e = t + i * EDGE_Q;
            int s = ei[e];
            int d = ei[N_EDGES + e];
            int pos = atomicAdd(&g_cur[d], 1);
            g_col[pos] = s;
        }
    }
}

// ---------------- GIN aggregation (bf16 in, fp32 acc, bf16 out) ----------
__global__ void k_agg(const float* __restrict__ eps, int layer) {
    int gt = blockIdx.x * blockDim.x + threadIdx.x;
    int node = gt >> 5;
    if (node >= N_NODES) return;
    int lane = gt & 31;
    float epsv = 1.0f + eps[layer];
    const uint2* hb = (const uint2*)g_hb;
    uint2 sv = hb[(size_t)node * 32 + lane];
    float4 acc;
    acc.x = bflo(sv.x) * epsv; acc.y = bfhi(sv.x) * epsv;
    acc.z = bflo(sv.y) * epsv; acc.w = bfhi(sv.y) * epsv;
    int e = g_off[node], end = g_off[node + 1];
    for (; e + 3 < end; e += 4) {
        int c0 = g_col[e], c1 = g_col[e + 1], c2 = g_col[e + 2], c3 = g_col[e + 3];
        uint2 v0 = hb[(size_t)c0 * 32 + lane];
        uint2 v1 = hb[(size_t)c1 * 32 + lane];
        uint2 v2 = hb[(size_t)c2 * 32 + lane];
        uint2 v3 = hb[(size_t)c3 * 32 + lane];
        acc.x += (bflo(v0.x) + bflo(v1.x)) + (bflo(v2.x) + bflo(v3.x));
        acc.y += (bfhi(v0.x) + bfhi(v1.x)) + (bfhi(v2.x) + bfhi(v3.x));
        acc.z += (bflo(v0.y) + bflo(v1.y)) + (bflo(v2.y) + bflo(v3.y));
        acc.w += (bfhi(v0.y) + bfhi(v1.y)) + (bfhi(v2.y) + bfhi(v3.y));
    }
    for (; e < end; e++) {
        int c = g_col[e];
        uint2 v = hb[(size_t)c * 32 + lane];
        acc.x += bflo(v.x); acc.y += bfhi(v.x);
        acc.z += bflo(v.y); acc.w += bfhi(v.y);
    }
    uint2 o;
    o.x = bfpack(acc.x, acc.y);
    o.y = bfpack(acc.z, acc.w);
    ((uint2*)g_aggb)[(size_t)node * 32 + lane] = o;
}

// ---------------- fused layer via mma.sync (HMMA bf16, f32 acc) ----------
// TILE 192 x 128, 384 threads (12 warps), warp tile 32x64. Grid 131 = 1 wave.
#define FM 192
#define APITCHB 272                 // bytes per A/W row (136 bf16)
#define OFF_W1H 52224               // 192*272
#define OFF_W1L (OFF_W1H + 34816)   // 128*272
#define OFF_W2H (OFF_W1L + 34816)
#define OFF_W2L (OFF_W2H + 34816)
#define OFF_CONS (OFF_W2L + 34816)  // 191488
#define FUSED_SMEM (OFF_CONS + 1536)

__device__ __forceinline__ void gemm_tile(
    uint32_t aB0, uint32_t aB1, uint32_t wHiB, uint32_t wLoB, float acc[2][8][4])
{
    #pragma unroll
    for (int k0 = 0; k0 < 128; k0 += 16) {
        uint a0[4], a1[4];
        ldsm4(a0, aB0 + k0 * 2);
        ldsm4(a1, aB1 + k0 * 2);
        #pragma unroll
        for (int np = 0; np < 4; np++) {
            uint b[4];
            ldsm4t(b, wHiB + k0 * APITCHB + np * 32);
            mma16816(acc[0][2*np],     a0, b);
            mma16816(acc[0][2*np + 1], a0, b + 2);
            mma16816(acc[1][2*np],     a1, b);
            mma16816(acc[1][2*np + 1], a1, b + 2);
            ldsm4t(b, wLoB + k0 * APITCHB + np * 32);
            mma16816(acc[0][2*np],     a0, b);
            mma16816(acc[0][2*np + 1], a0, b + 2);
            mma16816(acc[1][2*np],     a1, b);
            mma16816(acc[1][2*np + 1], a1, b + 2);
        }
    }
}

template <int LAST>
__global__ void __launch_bounds__(384, 1) k_fused(
    int layer, int M,
    const float* __restrict__ b1, const float* __restrict__ gamma,
    const float* __restrict__ beta, const float* __restrict__ mean,
    const float* __restrict__ var, const float* __restrict__ b2)
{
    extern __shared__ char sm[];
    float* cons = (float*)(sm + OFF_CONS);
    int tid = threadIdx.x;
    int m0 = blockIdx.x * FM;
    uint32_t sb = smem_u32(sm);

    // ---- weights via cp.async: group0 = W1 hi+lo, group1 = W2 hi+lo ----
    {
        const char* w1h = (const char*)g_whi[layer][0];
        const char* w1l = (const char*)g_wlo[layer][0];
        const char* w2h = (const char*)g_whi[layer][1];
        const char* w2l = (const char*)g_wlo[layer][1];
        for (int i = tid; i < 2176; i += 384) {
            cpa16(sb + OFF_W1H + i * 16, w1h + i * 16);
            cpa16(sb + OFF_W1L + i * 16, w1l + i * 16);
        }
        CPA_COMMIT();
        for (int i = tid; i < 2176; i += 384) {
            cpa16(sb + OFF_W2H + i * 16, w2h + i * 16);
            cpa16(sb + OFF_W2L + i * 16, w2l + i * 16);
        }
        CPA_COMMIT();
    }
    // ---- A tile: bf16 from g_aggb, 16B chunks, padded pitch ----
    {
        #pragma unroll
        for (int i = 0; i < 8; i++) {
            int idx = tid + i * 384;          // 0..3071
            int r = idx >> 4, c16 = idx & 15;
            int row = m0 + r;
            uint4 v = (row < M) ? *(const uint4*)(g_aggb + (size_t)row * 64 + c16 * 4)
                                : make_uint4(0, 0, 0, 0);
            *(uint4*)(sm + r * APITCHB + c16 * 16) = v;
        }
        if (tid < 128) {
            float s = gamma[tid] * rsqrtf(var[tid] + 1e-5f);
            cons[tid]       = s;
            cons[128 + tid] = (b1[tid] - mean[tid]) * s + beta[tid];
            cons[256 + tid] = b2[tid];
        }
    }
    CPA_WAIT(1);           // W1 hi/lo landed
    __syncthreads();

    int warp = tid >> 5;
    int lane = tid & 31;
    int mBase = (warp % 6) * 32;
    int nBase = (warp / 6) * 64;
    int lr  = lane & 15;
    int lc8 = (lane >> 4) << 3;
    int g = lane >> 2, t = lane & 3;

    uint32_t aB0 = sb + (mBase + lr) * APITCHB + lc8 * 2;
    uint32_t aB1 = aB0 + 16 * APITCHB;
    uint32_t wRow = lr * APITCHB + (nBase + lc8) * 2;

    float acc[2][8][4];
    #pragma unroll
    for (int mt = 0; mt < 2; mt++)
        #pragma unroll
        for (int ng = 0; ng < 8; ng++)
            #pragma unroll
            for (int i = 0; i < 4; i++) acc[mt][ng][i] = 0.f;

    // ---- GEMM1 ----
    gemm_tile(aB0, aB1, sb + OFF_W1H + wRow, sb + OFF_W1L + wRow, acc);

    // ---- BN + ReLU -> z overwrites A ----
    CPA_WAIT(0);           // W2 hi/lo landed
    __syncthreads();       // all A reads complete
    #pragma unroll
    for (int mt = 0; mt < 2; mt++) {
        int r0 = mBase + mt * 16 + g;
        #pragma unroll
        for (int ng = 0; ng < 8; ng++) {
            int colL = nBase + ng * 8 + 2 * t;
            float s0 = cons[colL], s1 = cons[colL + 1];
            float t0 = cons[128 + colL], t1 = cons[128 + colL + 1];
            float z00 = fmaxf(fmaf(acc[mt][ng][0], s0, t0), 0.f);
            float z01 = fmaxf(fmaf(acc[mt][ng][1], s1, t1), 0.f);
            float z10 = fmaxf(fmaf(acc[mt][ng][2], s0, t0), 0.f);
            float z11 = fmaxf(fmaf(acc[mt][ng][3], s1, t1), 0.f);
            *(uint*)(sm + r0 * APITCHB + colL * 2)       = bfpack(z00, z01);
            *(uint*)(sm + (r0 + 8) * APITCHB + colL * 2) = bfpack(z10, z11);
        }
    }
    __syncthreads();

    // ---- GEMM2 ----
    #pragma unroll
    for (int mt = 0; mt < 2; mt++)
        #pragma unroll
        for (int ng = 0; ng < 8; ng++)
            #pragma unroll
            for (int i = 0; i < 4; i++) acc[mt][ng][i] = 0.f;
    gemm_tile(aB0, aB1, sb + OFF_W2H + wRow, sb + OFF_W2L + wRow, acc);

    // ---- bias + ReLU -> output ----
    #pragma unroll
    for (int mt = 0; mt < 2; mt++) {
        int r0 = m0 + mBase + mt * 16 + g;
        #pragma unroll
        for (int ng = 0; ng < 8; ng++) {
            int colL = nBase + ng * 8 + 2 * t;
            float bb0 = cons[256 + colL], bb1 = cons[256 + colL + 1];
            float o00 = fmaxf(acc[mt][ng][0] + bb0, 0.f);
            float o01 = fmaxf(acc[mt][ng][1] + bb1, 0.f);
            float o10 = fmaxf(acc[mt][ng][2] + bb0, 0.f);
            float o11 = fmaxf(acc[mt][ng][3] + bb1, 0.f);
            if (LAST) {
                if (r0 < M)     *(float2*)(g_h + (size_t)r0 * D + colL)       = make_float2(o00, o01);
                if (r0 + 8 < M) *(float2*)(g_h + (size_t)(r0 + 8) * D + colL) = make_float2(o10, o11);
            } else {
                if (r0 < M)     g_hb[(size_t)r0 * 64 + colL / 2]       = bfpack(o00, o01);
                if (r0 + 8 < M) g_hb[(size_t)(r0 + 8) * 64 + colL / 2] = bfpack(o10, o11);
            }
        }
    }
}

// ---------------- mean-pool per graph + final linear ----------------
__global__ void k_pool(const float* __restrict__ h, const int* __restrict__ batch,
                       const float* __restrict__ Wout, const float* __restrict__ bout,
                       float* __restrict__ out)
{
    int g = blockIdx.x;
    int t = threadIdx.x;   // 128

    int lo = 0, hi = N_NODES;
    while (lo < hi) { int mid = (lo + hi) >> 1; if (batch[mid] < g) lo = mid + 1; else hi = mid; }
    int start = lo;
    lo = start; hi = N_NODES;
    while (lo < hi) { int mid = (lo + hi) >> 1; if (batch[mid] < g + 1) lo = mid + 1; else hi = mid; }
    int stop = lo;

    float s = 0.f;
    for (int n = start; n < stop; n++) s += h[(size_t)n * D + t];
    float cnt = fmaxf((float)(stop - start), 1.f);

    __shared__ float sp[D];
    sp[t] = s / cnt;
    __syncthreads();

    if (t < D_OUT) {
        float acc = bout[t];
        #pragma unroll 8
        for (int k = 0; k < D; k++) acc += sp[k] * Wout[k * D_OUT + t];
        out[g * D_OUT + t] = acc;
    }
}

// ---------------- host launcher ----------------
extern "C" void kernel_launch(void* const* d_in, const int* in_sizes, int n_in,
                              void* d_out, int out_size)
{
    const float* x     = (const float*)d_in[0];
    const int*   ei    = (const int*)d_in[1];
    const int*   batch = (const int*)d_in[2];
    const float* W1    = (const float*)d_in[3];
    const float* b1    = (const float*)d_in[4];
    const float* gamma = (const float*)d_in[5];
    const float* beta  = (const float*)d_in[6];
    const float* rmean = (const float*)d_in[7];
    const float* rvar  = (const float*)d_in[8];
    const float* W2    = (const float*)d_in[9];
    const float* b2    = (const float*)d_in[10];
    const float* eps   = (const float*)d_in[11];
    const float* Wout  = (const float*)d_in[12];
    const float* bout  = (const float*)d_in[13];
    float* out = (float*)d_out;

    float* p_h;
    int* p_deg;
    cudaGetSymbolAddress((void**)&p_h,   g_h);
    cudaGetSymbolAddress((void**)&p_deg, g_deg);

    cudaFuncSetAttribute(k_fused<0>, cudaFuncAttributeMaxDynamicSharedMemorySize, FUSED_SMEM);
    cudaFuncSetAttribute(k_fused<1>, cudaFuncAttributeMaxDynamicSharedMemorySize, FUSED_SMEM);

    // ---- prep (deterministic every call) ----
    cudaMemsetAsync(p_deg, 0, N_NODES * sizeof(int));
    k_cvt<<<(N_NODES * D / 8 + 255) / 256, 256>>>(x);
    k_wcvt<<<(3 * 2 * 128 * 64 + 255) / 256, 256>>>(W1, W2);
    k_hist<<<(EDGE_Q + 255) / 256, 256>>>(ei);
    k_scan_a<<<SCAN_BLOCKS, 1024>>>();
    k_scan_b<<<1, 32>>>();
    k_scan_c<<<SCAN_BLOCKS, 1024>>>();
    k_fill<<<(EDGE_Q + 255) / 256, 256>>>(ei);

    const int fused_blocks = (N_NODES + FM - 1) / FM;    // 131
    const int agg_blocks   = (N_NODES * 32 + 255) / 256;

    for (int l = 0; l < N_LAYERS; l++) {
        k_agg<<<agg_blocks, 256>>>(eps, l);
        if (l < N_LAYERS - 1) {
            k_fused<0><<<fused_blocks, 384, FUSED_SMEM>>>(
                l, N_NODES, b1 + l * D, gamma + l * D, beta + l * D,
                rmean + l * D, rvar + l * D, b2 + l * D);
        } else {
            k_fused<1><<<fused_blocks, 384, FUSED_SMEM>>>(
                l, N_NODES, b1 + l * D, gamma + l * D, beta + l * D,
                rmean + l * D, rvar + l * D, b2 + l * D);
        }
    }

    k_pool<<<N_GRAPHS, D>>>(p_h, batch, Wout, bout, out);
}